// round 9
// baseline (speedup 1.0000x reference)
#include <cuda_runtime.h>
#include <cuda_bf16.h>
#include <math.h>
#include <stdint.h>

// Problem constants
#define TOK   4096      // B*S
#define DIM   1024      // D == R
#define SEQ   2048
#define NBATCH 2
#define NH    8
#define DHEAD 128
#define NEXP  8
#define NPROC 32
#define TOPK  3
#define KTOT  8192      // NEXP * DIM

// GEMM tiling: CTA 128(M) x 64(N) x 32(K), 2 CTAs/SM
#define BK      32
#define NCHUNK  (KTOT / BK)           // 256
#define PADH    40                    // smem row stride in bf16 halves (80B, 16B-aligned)
#define AHI_OFF 0
#define ALO_OFF (128 * PADH * 2)              // 10240
#define BHI_OFF (2 * ALO_OFF)                 // 20480
#define BLO_OFF (BHI_OFF + 64 * PADH * 2)     // 25600
#define STAGE_BYTES (BLO_OFF + 64 * PADH * 2) // 30720
#define NSTAGE  3
#define SMEM_GEMM_BYTES (NSTAGE * STAGE_BYTES)   // 92160

// ---------------------------------------------------------------------------
// Scratch (device globals — no runtime allocation allowed)
// ---------------------------------------------------------------------------
__device__ float g_h  [TOK * DIM];
__device__ float g_Q  [TOK * DIM];
__device__ float g_Kc [TOK * DIM];
__device__ float g_V  [TOK * DIM];
__device__ float g_O  [TOK * DIM];
__device__ float g_inw [TOK * NEXP];
__device__ float g_outw[TOK * NEXP];
__device__ int   g_pidx[TOK * TOPK];
__device__ __nv_bfloat16 g_whi[DIM * KTOT];   // weightT hi [N=1024, K=8192]
__device__ __nv_bfloat16 g_wlo[DIM * KTOT];
__device__ __nv_bfloat16 g_xhi[TOK * DIM];    // activation split (x / O)
__device__ __nv_bfloat16 g_xlo[TOK * DIM];
__device__ __nv_bfloat16 g_hhi[TOK * DIM];    // householder output split
__device__ __nv_bfloat16 g_hlo[TOK * DIM];

// ---------------------------------------------------------------------------
// Portable tensor-core helpers (sm_80+ PTX; no 'a'-suffix features)
// ---------------------------------------------------------------------------
#define LDSM4(r0, r1, r2, r3, addr) \
    asm volatile("ldmatrix.sync.aligned.m8n8.x4.shared.b16 {%0,%1,%2,%3}, [%4];" \
                 : "=r"(r0), "=r"(r1), "=r"(r2), "=r"(r3) : "r"(addr))

__device__ __forceinline__ void mma_bf16(float* c, const uint32_t* a, const uint32_t* b) {
    asm volatile(
        "mma.sync.aligned.m16n8k16.row.col.f32.bf16.bf16.f32 "
        "{%0,%1,%2,%3}, {%4,%5,%6,%7}, {%8,%9}, {%0,%1,%2,%3};"
        : "+f"(c[0]), "+f"(c[1]), "+f"(c[2]), "+f"(c[3])
        : "r"(a[0]), "r"(a[1]), "r"(a[2]), "r"(a[3]), "r"(b[0]), "r"(b[1]));
}

__device__ __forceinline__ void cp16(uint32_t saddr, const void* gaddr) {
    asm volatile("cp.async.cg.shared.global [%0], [%1], 16;" :: "r"(saddr), "l"(gaddr));
}
__device__ __forceinline__ void cp_commit() {
    asm volatile("cp.async.commit_group;" ::: "memory");
}
template <int N>
__device__ __forceinline__ void cp_wait() {
    asm volatile("cp.async.wait_group %0;" :: "n"(N) : "memory");
}

__device__ __forceinline__ void split_bf16(float v, __nv_bfloat16& hi, __nv_bfloat16& lo) {
    hi = __float2bfloat16_rn(v);
    lo = __float2bfloat16_rn(v - __bfloat162float(hi));
}

// ---------------------------------------------------------------------------
// Weight prep: W[KTOT, DIM] fp32 -> transposed bf16 hi/lo [DIM, KTOT]
// ---------------------------------------------------------------------------
__global__ void prep_w_kernel(const float* __restrict__ W,
                              __nv_bfloat16* __restrict__ Whi,
                              __nv_bfloat16* __restrict__ Wlo)
{
    __shared__ float ts[32][33];
    int k0 = blockIdx.y * 32, n0 = blockIdx.x * 32;
    int tx = threadIdx.x & 31, ty = threadIdx.x >> 5;   // 32 x 8
    #pragma unroll
    for (int r = 0; r < 4; r++) {
        int k = ty + r * 8;
        ts[k][tx] = W[(size_t)(k0 + k) * DIM + n0 + tx];
    }
    __syncthreads();
    #pragma unroll
    for (int r = 0; r < 4; r++) {
        int n = ty + r * 8;
        float v = ts[tx][n];                      // W[k0+tx][n0+n]
        __nv_bfloat16 h, l;
        split_bf16(v, h, l);
        size_t o = (size_t)(n0 + n) * KTOT + k0 + tx;
        Whi[o] = h;
        Wlo[o] = l;
    }
}

// ---------------------------------------------------------------------------
// Activation split: fp32 [TOK,DIM] -> bf16 hi/lo
// ---------------------------------------------------------------------------
__global__ void split_kernel(const float* __restrict__ src,
                             __nv_bfloat16* __restrict__ hi,
                             __nv_bfloat16* __restrict__ lo)
{
    int i = (blockIdx.x * 256 + threadIdx.x) * 4;
    float4 v = *(const float4*)(src + i);
    __nv_bfloat16 h[4], l[4];
    split_bf16(v.x, h[0], l[0]);
    split_bf16(v.y, h[1], l[1]);
    split_bf16(v.z, h[2], l[2]);
    split_bf16(v.w, h[3], l[3]);
    *(uint64_t*)(hi + i) = *(uint64_t*)h;
    *(uint64_t*)(lo + i) = *(uint64_t*)l;
}

// ---------------------------------------------------------------------------
// Tensor-core mixture GEMM via mma.sync (split-bf16, 3 passes, fp32 acc).
// CTA 128x64xBK32, 256 threads / 8 warps (4M x 2N), 32x32 warp tiles,
// 3-stage cp.async pipeline, 2 CTAs per SM for cross-CTA latency hiding.
// ---------------------------------------------------------------------------
__global__ __launch_bounds__(256, 2)
void circuit_gemm_tc(const __nv_bfloat16* __restrict__ Ahi,  // [TOK, DIM]
                     const __nv_bfloat16* __restrict__ Alo,
                     const __nv_bfloat16* __restrict__ Whi,  // [N, K]
                     const __nv_bfloat16* __restrict__ Wlo,
                     const float* __restrict__ wgt,          // [TOK, NEXP]
                     float* __restrict__ out)                // [TOK, DIM]
{
    extern __shared__ char smem[];
    __shared__ float swgt[128 * NEXP];
    const uint32_t sb = (uint32_t)__cvta_generic_to_shared(smem);
    int tid = threadIdx.x, lane = tid & 31, wid = tid >> 5;
    int bm = blockIdx.y * 128, bn = blockIdx.x * 64;

    // ---- loader role ----
    // A: 2 threads per row, 16-k half each; B: 4 threads per row, 8-k quarter
    int ra = tid >> 1, ka = (tid & 1) * 16;
    int rb = tid >> 2, kb2 = (tid & 3) * 8;
    const __nv_bfloat16* ahip = Ahi + (size_t)(bm + ra) * DIM + ka;
    const __nv_bfloat16* alop = Alo + (size_t)(bm + ra) * DIM + ka;
    const __nv_bfloat16* bhip = Whi + (size_t)(bn + rb) * KTOT + kb2;
    const __nv_bfloat16* blop = Wlo + (size_t)(bn + rb) * KTOT + kb2;
    const uint32_t aoff = (uint32_t)(ra * PADH + ka) * 2;
    const uint32_t boff = (uint32_t)(rb * PADH + kb2) * 2;

    auto load_chunk = [&](int c) {
        uint32_t st = sb + (uint32_t)(c % NSTAGE) * STAGE_BYTES;
        int k0 = c * BK;
        int d0 = k0 & (DIM - 1);
        cp16(st + AHI_OFF + aoff,      ahip + d0);
        cp16(st + AHI_OFF + aoff + 16, ahip + d0 + 8);
        cp16(st + ALO_OFF + aoff,      alop + d0);
        cp16(st + ALO_OFF + aoff + 16, alop + d0 + 8);
        cp16(st + BHI_OFF + boff, bhip + k0);
        cp16(st + BLO_OFF + boff, blop + k0);
        cp_commit();
    };

    // ---- compute role: 4(M) x 2(N) warp grid, 32x32 warp tile ----
    int wm = (wid >> 1) * 32;
    int wn = (wid & 1) * 32;
    int arow = lane & 15;
    int acol = (lane >> 4) * 8;
    int q    = lane >> 3, rl = lane & 7;
    int brow = wn + ((q >= 2) ? 8 : 0) + rl;
    int bcol = (q & 1) * 8;
    const uint32_t aOff = AHI_OFF + (uint32_t)((wm + arow) * PADH + acol) * 2;
    const uint32_t bOff = BHI_OFF + (uint32_t)(brow * PADH + bcol) * 2;
    int g = lane >> 2;

    float acc[2][4][4];
    float seg[2][4][4];
    #pragma unroll
    for (int i = 0; i < 2; i++)
        #pragma unroll
        for (int j = 0; j < 4; j++)
            #pragma unroll
            for (int e = 0; e < 4; e++) acc[i][j][e] = 0.f;

    // ---- prologue ----
    for (int idx = tid; idx < 128 * NEXP; idx += 256)
        swgt[idx] = wgt[(size_t)(bm + (idx >> 3)) * NEXP + (idx & 7)];
    load_chunk(0);
    load_chunk(1);

    int c = 0;
    for (int e = 0; e < NEXP; e++) {
        #pragma unroll
        for (int i = 0; i < 2; i++)
            #pragma unroll
            for (int j = 0; j < 4; j++)
                #pragma unroll
                for (int t = 0; t < 4; t++) seg[i][j][t] = 0.f;

        for (int dc = 0; dc < 32; dc++, c++) {
            if (c + 1 < NCHUNK) cp_wait<1>(); else cp_wait<0>();
            __syncthreads();
            if (c + 2 < NCHUNK) load_chunk(c + 2);

            uint32_t st = sb + (uint32_t)(c % NSTAGE) * STAGE_BYTES;
            uint32_t aHi = st + aOff;
            uint32_t bHi = st + bOff;

            #pragma unroll
            for (int ks = 0; ks < 2; ks++) {
                uint32_t kb = (uint32_t)(ks * 16) * 2;
                uint32_t bh[4][2], bl[4][2];
                #pragma unroll
                for (int p = 0; p < 2; p++) {
                    uint32_t ba = bHi + (uint32_t)(p * 16 * PADH) * 2 + kb;
                    LDSM4(bh[2*p][0], bh[2*p][1], bh[2*p+1][0], bh[2*p+1][1], ba);
                    LDSM4(bl[2*p][0], bl[2*p][1], bl[2*p+1][0], bl[2*p+1][1],
                          ba + (BLO_OFF - BHI_OFF));
                }
                uint32_t ah[2][4], al[2][4];
                #pragma unroll
                for (int mt = 0; mt < 2; mt++) {
                    uint32_t aa = aHi + (uint32_t)(mt * 16 * PADH) * 2 + kb;
                    LDSM4(ah[mt][0], ah[mt][1], ah[mt][2], ah[mt][3], aa);
                    LDSM4(al[mt][0], al[mt][1], al[mt][2], al[mt][3],
                          aa + (ALO_OFF - AHI_OFF));
                }
                // pass-major: 8 independent accumulators between same-acc reuse
                #pragma unroll
                for (int mt = 0; mt < 2; mt++)
                    #pragma unroll
                    for (int nt = 0; nt < 4; nt++)
                        mma_bf16(seg[mt][nt], ah[mt], bh[nt]);
                #pragma unroll
                for (int mt = 0; mt < 2; mt++)
                    #pragma unroll
                    for (int nt = 0; nt < 4; nt++)
                        mma_bf16(seg[mt][nt], ah[mt], bl[nt]);
                #pragma unroll
                for (int mt = 0; mt < 2; mt++)
                    #pragma unroll
                    for (int nt = 0; nt < 4; nt++)
                        mma_bf16(seg[mt][nt], al[mt], bh[nt]);
            }
        }

        // ---- expert boundary: acc += w(row, e) * seg ----
        #pragma unroll
        for (int mt = 0; mt < 2; mt++) {
            float w0 = swgt[(wm + mt * 16 + g) * NEXP + e];
            float w1 = swgt[(wm + mt * 16 + 8 + g) * NEXP + e];
            #pragma unroll
            for (int nt = 0; nt < 4; nt++) {
                acc[mt][nt][0] += w0 * seg[mt][nt][0];
                acc[mt][nt][1] += w0 * seg[mt][nt][1];
                acc[mt][nt][2] += w1 * seg[mt][nt][2];
                acc[mt][nt][3] += w1 * seg[mt][nt][3];
            }
        }
    }

    // ---- epilogue ----
    int tig = lane & 3;
    #pragma unroll
    for (int mt = 0; mt < 2; mt++) {
        #pragma unroll
        for (int nt = 0; nt < 4; nt++) {
            int row = bm + wm + mt * 16 + g;
            int col = bn + wn + nt * 8 + tig * 2;
            *(float2*)(out + (size_t)row * DIM + col) =
                make_float2(acc[mt][nt][0], acc[mt][nt][1]);
            *(float2*)(out + (size_t)(row + 8) * DIM + col) =
                make_float2(acc[mt][nt][2], acc[mt][nt][3]);
        }
    }
}

// ---------------------------------------------------------------------------
// Router: 48 logits per token (8 in / 32 proc / 8 out), softmax8 x2 + top-3
// ---------------------------------------------------------------------------
__global__ void router_kernel(const float* __restrict__ act,
                              const float* __restrict__ Wi,
                              const float* __restrict__ Wp,
                              const float* __restrict__ Wo,
                              float* __restrict__ inw,
                              int*   __restrict__ pidx,
                              float* __restrict__ outw)
{
    int t    = blockIdx.x;
    int tid  = threadIdx.x;
    int lane = tid & 31, warp = tid >> 5;
    __shared__ float xs[DIM];
    __shared__ float lg[48];

    const float* xr = act + (size_t)t * DIM;
    for (int i = tid; i < DIM; i += 128) xs[i] = xr[i];
    __syncthreads();

    for (int l = warp; l < 48; l += 4) {
        const float* wr = (l < 8) ? (Wi + (size_t)l * DIM)
                        : (l < 40) ? (Wp + (size_t)(l - 8) * DIM)
                                   : (Wo + (size_t)(l - 40) * DIM);
        float s = 0.f;
        for (int d = lane; d < DIM; d += 32) s += xs[d] * wr[d];
        #pragma unroll
        for (int off = 16; off > 0; off >>= 1)
            s += __shfl_xor_sync(0xffffffffu, s, off);
        if (lane == 0) lg[l] = s;
    }
    __syncthreads();

    if (tid == 0) {
        float m = lg[0];
        for (int i = 1; i < 8; i++) m = fmaxf(m, lg[i]);
        float e[8], sum = 0.f;
        for (int i = 0; i < 8; i++) { e[i] = expf(lg[i] - m); sum += e[i]; }
        for (int i = 0; i < 8; i++) inw[t * 8 + i] = e[i] / sum;

        bool used[NPROC];
        for (int n = 0; n < NPROC; n++) used[n] = false;
        for (int r = 0; r < TOPK; r++) {
            float best = -INFINITY; int bi = 0;
            for (int n = 0; n < NPROC; n++)
                if (!used[n] && lg[8 + n] > best) { best = lg[8 + n]; bi = n; }
            used[bi] = true;
            pidx[t * TOPK + r] = bi;
        }

        m = lg[40];
        for (int i = 1; i < 8; i++) m = fmaxf(m, lg[40 + i]);
        sum = 0.f;
        for (int i = 0; i < 8; i++) { e[i] = expf(lg[40 + i] - m); sum += e[i]; }
        for (int i = 0; i < 8; i++) outw[t * 8 + i] = e[i] / sum;
    }
}

// ---------------------------------------------------------------------------
// Householder reflections: h -= 2 (h.v)/(v.v + 1e-8) v, 3x per token;
// writes split bf16 hi/lo output.
// ---------------------------------------------------------------------------
__global__ void householder_kernel(const float* __restrict__ hbuf,
                                   const float* __restrict__ vproc,
                                   const int* __restrict__ pidx,
                                   __nv_bfloat16* __restrict__ ohi,
                                   __nv_bfloat16* __restrict__ olo)
{
    int t = blockIdx.x, tid = threadIdx.x;
    int lane = tid & 31, warp = tid >> 5;
    const float* hr = hbuf + (size_t)t * DIM;

    float hv[4];
    #pragma unroll
    for (int i = 0; i < 4; i++) hv[i] = hr[tid + 256 * i];

    __shared__ float sred[16];

    for (int rfl = 0; rfl < TOPK; rfl++) {
        int idx = pidx[t * TOPK + rfl];
        const float* v = vproc + (size_t)idx * DIM;
        float vr[4];
        float d1 = 0.f, d2 = 0.f;
        #pragma unroll
        for (int i = 0; i < 4; i++) {
            vr[i] = v[tid + 256 * i];
            d1 += hv[i] * vr[i];
            d2 += vr[i] * vr[i];
        }
        #pragma unroll
        for (int off = 16; off > 0; off >>= 1) {
            d1 += __shfl_xor_sync(0xffffffffu, d1, off);
            d2 += __shfl_xor_sync(0xffffffffu, d2, off);
        }
        if (lane == 0) { sred[warp] = d1; sred[8 + warp] = d2; }
        __syncthreads();
        float t1 = 0.f, t2 = 0.f;
        #pragma unroll
        for (int w = 0; w < 8; w++) { t1 += sred[w]; t2 += sred[8 + w]; }
        float f = 2.f * t1 / (t2 + 1e-8f);
        #pragma unroll
        for (int i = 0; i < 4; i++) hv[i] -= f * vr[i];
        __syncthreads();
    }

    #pragma unroll
    for (int i = 0; i < 4; i++) {
        __nv_bfloat16 h, l;
        split_bf16(hv[i], h, l);
        ohi[(size_t)t * DIM + tid + 256 * i] = h;
        olo[(size_t)t * DIM + tid + 256 * i] = l;
    }
}

// ---------------------------------------------------------------------------
// Causal attention, online softmax (fp32). Lane-per-key within 32-key
// batches: one exp per lane per batch, one shfl broadcast per key for P.V.
// ---------------------------------------------------------------------------
__global__ void attn_kernel(const float* __restrict__ Q,
                            const float* __restrict__ K,
                            const float* __restrict__ V,
                            float* __restrict__ O)
{
    const float scale = 0.08838834764831845f;  // 1/sqrt(128)
    int bh = blockIdx.y;
    int b = bh >> 3, hh = bh & 7;
    int q0 = blockIdx.x * 8;
    int tid = threadIdx.x, lane = tid & 31, warp = tid >> 5;

    const float* Qb = Q + (size_t)b * SEQ * DIM + hh * DHEAD;
    const float* Kb = K + (size_t)b * SEQ * DIM + hh * DHEAD;
    const float* Vb = V + (size_t)b * SEQ * DIM + hh * DHEAD;
    float*       Ob = O + (size_t)b * SEQ * DIM + hh * DHEAD;

    __shared__ float Ks[32][132];   // pad 132: conflict-free per-row float4
    __shared__ float Vs[32][132];
    __shared__ float qs[8][128];

    int qrow = q0 + warp;
    #pragma unroll
    for (int i = 0; i < 4; i++)
        qs[warp][lane + 32 * i] = Qb[(size_t)qrow * DIM + lane + 32 * i];

    float acc[4] = {0.f, 0.f, 0.f, 0.f};   // dims lane*4 .. lane*4+3
    float mi = -1e30f, li = 0.f;

    int kend = q0 + 8;   // need keys [0, kend)
    for (int c0 = 0; c0 < kend; c0 += 32) {
        __syncthreads();
        for (int idx = tid; idx < 32 * DHEAD; idx += 256) {
            int j = idx >> 7, d = idx & 127;
            Ks[j][d] = Kb[(size_t)(c0 + j) * DIM + d];
            Vs[j][d] = Vb[(size_t)(c0 + j) * DIM + d];
        }
        __syncthreads();

        int kg = c0 + lane;
        const float4* kr = (const float4*)&Ks[lane][0];
        const float4* qr = (const float4*)&qs[warp][0];
        float s = 0.f;
        #pragma unroll
        for (int w = 0; w < 32; w++) {
            float4 kk = kr[w];
            float4 qq = qr[w];
            s += qq.x * kk.x + qq.y * kk.y + qq.z * kk.z + qq.w * kk.w;
        }
        s *= scale;
        if (kg > qrow) s = -1e30f;   // causal mask (exp -> exact 0)

        float mb = s;
        #pragma unroll
        for (int off = 16; off > 0; off >>= 1)
            mb = fmaxf(mb, __shfl_xor_sync(0xffffffffu, mb, off));
        float mnew = fmaxf(mi, mb);
        float corr = expf(mi - mnew);
        float p = expf(s - mnew);
        float psum = p;
        #pragma unroll
        for (int off = 16; off > 0; off >>= 1)
            psum += __shfl_xor_sync(0xffffffffu, psum, off);
        li = li * corr + psum;

        #pragma unroll
        for (int i = 0; i < 4; i++) acc[i] *= corr;
        #pragma unroll
        for (int j = 0; j < 32; j++) {
            float pj = __shfl_sync(0xffffffffu, p, j);
            float4 vv = *(const float4*)&Vs[j][lane * 4];
            acc[0] += pj * vv.x;
            acc[1] += pj * vv.y;
            acc[2] += pj * vv.z;
            acc[3] += pj * vv.w;
        }
        mi = mnew;
    }

    float inv = 1.f / li;
    float4 o4 = make_float4(acc[0] * inv, acc[1] * inv, acc[2] * inv, acc[3] * inv);
    *(float4*)(Ob + (size_t)qrow * DIM + lane * 4) = o4;
}

// ---------------------------------------------------------------------------
// Launch
// ---------------------------------------------------------------------------
extern "C" void kernel_launch(void* const* d_in, const int* in_sizes, int n_in,
                              void* d_out, int out_size)
{
    const float* x       = (const float*)d_in[0];
    const float* Wr_in   = (const float*)d_in[2];
    const float* Wr_proc = (const float*)d_in[3];
    const float* Wr_out  = (const float*)d_in[4];
    const float* WrO_in  = (const float*)d_in[5];
    const float* WrO_proc= (const float*)d_in[6];
    const float* WrO_out = (const float*)d_in[7];
    const float* Wq_in   = (const float*)d_in[8];
    const float* vq      = (const float*)d_in[9];
    const float* Wq_out  = (const float*)d_in[10];
    const float* Wk_in   = (const float*)d_in[11];
    const float* vk      = (const float*)d_in[12];
    const float* Wk_out  = (const float*)d_in[13];
    const float* Wv_in   = (const float*)d_in[14];
    const float* vv      = (const float*)d_in[15];
    const float* Wv_out  = (const float*)d_in[16];
    const float* Wo_in   = (const float*)d_in[17];
    const float* vo      = (const float*)d_in[18];
    const float* Wo_out  = (const float*)d_in[19];
    float* out = (float*)d_out;

    float *h, *Q, *Kc, *V, *O, *inw, *outw;
    int* pidx;
    __nv_bfloat16 *whi, *wlo, *xhi, *xlo, *hhi, *hlo;
    cudaGetSymbolAddress((void**)&h,    g_h);
    cudaGetSymbolAddress((void**)&Q,    g_Q);
    cudaGetSymbolAddress((void**)&Kc,   g_Kc);
    cudaGetSymbolAddress((void**)&V,    g_V);
    cudaGetSymbolAddress((void**)&O,    g_O);
    cudaGetSymbolAddress((void**)&inw,  g_inw);
    cudaGetSymbolAddress((void**)&outw, g_outw);
    cudaGetSymbolAddress((void**)&pidx, g_pidx);
    cudaGetSymbolAddress((void**)&whi,  g_whi);
    cudaGetSymbolAddress((void**)&wlo,  g_wlo);
    cudaGetSymbolAddress((void**)&xhi,  g_xhi);
    cudaGetSymbolAddress((void**)&xlo,  g_xlo);
    cudaGetSymbolAddress((void**)&hhi,  g_hhi);
    cudaGetSymbolAddress((void**)&hlo,  g_hlo);

    cudaFuncSetAttribute(circuit_gemm_tc,
                         cudaFuncAttributeMaxDynamicSharedMemorySize,
                         SMEM_GEMM_BYTES);

    dim3 gGemm(DIM / 64, TOK / 128);      // (16, 32) = 512 CTAs
    dim3 gPrep(DIM / 32, KTOT / 32);      // (32, 256)
    int  gSplit = TOK * DIM / (256 * 4);  // 4096

    auto gemm = [&](const __nv_bfloat16* ah, const __nv_bfloat16* al,
                    const float* W, const float* wg, float* o) {
        prep_w_kernel<<<gPrep, 256>>>(W, whi, wlo);
        circuit_gemm_tc<<<gGemm, 256, SMEM_GEMM_BYTES>>>(ah, al, whi, wlo, wg, o);
    };

    // Router on x + x split
    router_kernel<<<TOK, 128>>>(x, Wr_in, Wr_proc, Wr_out, inw, pidx, outw);
    split_kernel<<<gSplit, 256>>>(x, xhi, xlo);

    // Q circuit
    gemm(xhi, xlo, Wq_in, inw, h);
    householder_kernel<<<TOK, 256>>>(h, vq, pidx, hhi, hlo);
    gemm(hhi, hlo, Wq_out, outw, Q);

    // K circuit
    gemm(xhi, xlo, Wk_in, inw, h);
    householder_kernel<<<TOK, 256>>>(h, vk, pidx, hhi, hlo);
    gemm(hhi, hlo, Wk_out, outw, Kc);

    // V circuit
    gemm(xhi, xlo, Wv_in, inw, h);
    householder_kernel<<<TOK, 256>>>(h, vv, pidx, hhi, hlo);
    gemm(hhi, hlo, Wv_out, outw, V);

    // Attention
    attn_kernel<<<dim3(SEQ / 8, NBATCH * NH), 256>>>(Q, Kc, V, O);

    // Router on O + output circuit (reuse x split buffers)
    router_kernel<<<TOK, 128>>>(O, WrO_in, WrO_proc, WrO_out, inw, pidx, outw);
    split_kernel<<<gSplit, 256>>>(O, xhi, xlo);
    gemm(xhi, xlo, Wo_in, inw, h);
    householder_kernel<<<TOK, 256>>>(h, vo, pidx, hhi, hlo);
    gemm(hhi, hlo, Wo_out, outw, out);

    (void)in_sizes; (void)n_in; (void)out_size;
}

// round 10
// speedup vs baseline: 1.1374x; 1.1374x over previous
#include <cuda_runtime.h>
#include <cuda_bf16.h>
#include <math.h>
#include <stdint.h>

// Problem constants
#define TOK   4096      // B*S
#define DIM   1024      // D == R
#define SEQ   2048
#define NBATCH 2
#define NH    8
#define DHEAD 128
#define NEXP  8
#define NPROC 32
#define TOPK  3
#define KTOT  8192      // NEXP * DIM
#define WSZ   ((size_t)DIM * KTOT)   // elements per weight slot
#define ASZ   ((size_t)TOK * DIM)

// GEMM tiling (R7 config: 128x128xBK64, 512 threads, 3 stages)
#define BK      64
#define NCHUNK  (KTOT / BK)           // 128
#define PAD     72                    // smem row stride in bf16 halves (144B)
#define MAT_BYTES   (128 * PAD * 2)   // 18432 per matrix
#define STAGE_BYTES (4 * MAT_BYTES)   // Ahi, Alo, Bhi, Blo
#define NSTAGE  3
#define SMEM_GEMM_BYTES (NSTAGE * STAGE_BYTES)   // 221184

// ---------------------------------------------------------------------------
// Scratch (device globals — no runtime allocation allowed)
// ---------------------------------------------------------------------------
__device__ float g_h  [3 * TOK * DIM];
__device__ float g_Q  [TOK * DIM];
__device__ float g_Kc [TOK * DIM];
__device__ float g_V  [TOK * DIM];
__device__ float g_O  [TOK * DIM];
__device__ float g_inw [TOK * NEXP];
__device__ float g_outw[TOK * NEXP];
__device__ int   g_pidx[TOK * TOPK];
__device__ __nv_bfloat16 g_whi[3 * DIM * KTOT];   // weightT hi, 3 slots
__device__ __nv_bfloat16 g_wlo[3 * DIM * KTOT];
__device__ __nv_bfloat16 g_xhi[TOK * DIM];        // activation split (x / O)
__device__ __nv_bfloat16 g_xlo[TOK * DIM];
__device__ __nv_bfloat16 g_hhi[3 * TOK * DIM];    // householder output split
__device__ __nv_bfloat16 g_hlo[3 * TOK * DIM];

// ---------------------------------------------------------------------------
// Portable tensor-core helpers (sm_80+ PTX; no 'a'-suffix features)
// ---------------------------------------------------------------------------
#define LDSM4(r0, r1, r2, r3, addr) \
    asm volatile("ldmatrix.sync.aligned.m8n8.x4.shared.b16 {%0,%1,%2,%3}, [%4];" \
                 : "=r"(r0), "=r"(r1), "=r"(r2), "=r"(r3) : "r"(addr))

__device__ __forceinline__ void mma_bf16(float* c, const uint32_t* a, const uint32_t* b) {
    asm volatile(
        "mma.sync.aligned.m16n8k16.row.col.f32.bf16.bf16.f32 "
        "{%0,%1,%2,%3}, {%4,%5,%6,%7}, {%8,%9}, {%0,%1,%2,%3};"
        : "+f"(c[0]), "+f"(c[1]), "+f"(c[2]), "+f"(c[3])
        : "r"(a[0]), "r"(a[1]), "r"(a[2]), "r"(a[3]), "r"(b[0]), "r"(b[1]));
}

__device__ __forceinline__ void cp16(uint32_t saddr, const void* gaddr) {
    asm volatile("cp.async.cg.shared.global [%0], [%1], 16;" :: "r"(saddr), "l"(gaddr));
}
__device__ __forceinline__ void cp_commit() {
    asm volatile("cp.async.commit_group;" ::: "memory");
}
template <int N>
__device__ __forceinline__ void cp_wait() {
    asm volatile("cp.async.wait_group %0;" :: "n"(N) : "memory");
}

__device__ __forceinline__ void split_bf16(float v, __nv_bfloat16& hi, __nv_bfloat16& lo) {
    hi = __float2bfloat16_rn(v);
    lo = __float2bfloat16_rn(v - __bfloat162float(hi));
}

// ---------------------------------------------------------------------------
// Weight prep (z-batched): W_z[KTOT, DIM] fp32 -> bf16 hi/lo [DIM, KTOT] slot z
// ---------------------------------------------------------------------------
__global__ void prep_w_kernel(const float* __restrict__ W0,
                              const float* __restrict__ W1,
                              const float* __restrict__ W2,
                              __nv_bfloat16* __restrict__ Whi,
                              __nv_bfloat16* __restrict__ Wlo)
{
    int z = blockIdx.z;
    const float* W = (z == 0) ? W0 : (z == 1) ? W1 : W2;
    __nv_bfloat16* whi = Whi + (size_t)z * WSZ;
    __nv_bfloat16* wlo = Wlo + (size_t)z * WSZ;

    __shared__ float ts[32][33];
    int k0 = blockIdx.y * 32, n0 = blockIdx.x * 32;
    int tx = threadIdx.x & 31, ty = threadIdx.x >> 5;   // 32 x 8
    #pragma unroll
    for (int r = 0; r < 4; r++) {
        int k = ty + r * 8;
        ts[k][tx] = W[(size_t)(k0 + k) * DIM + n0 + tx];
    }
    __syncthreads();
    #pragma unroll
    for (int r = 0; r < 4; r++) {
        int n = ty + r * 8;
        float v = ts[tx][n];                      // W[k0+tx][n0+n]
        __nv_bfloat16 h, l;
        split_bf16(v, h, l);
        size_t o = (size_t)(n0 + n) * KTOT + k0 + tx;
        whi[o] = h;
        wlo[o] = l;
    }
}

// ---------------------------------------------------------------------------
// Activation split: fp32 [TOK,DIM] -> bf16 hi/lo
// ---------------------------------------------------------------------------
__global__ void split_kernel(const float* __restrict__ src,
                             __nv_bfloat16* __restrict__ hi,
                             __nv_bfloat16* __restrict__ lo)
{
    int i = (blockIdx.x * 256 + threadIdx.x) * 4;
    float4 v = *(const float4*)(src + i);
    __nv_bfloat16 h[4], l[4];
    split_bf16(v.x, h[0], l[0]);
    split_bf16(v.y, h[1], l[1]);
    split_bf16(v.z, h[2], l[2]);
    split_bf16(v.w, h[3], l[3]);
    *(uint64_t*)(hi + i) = *(uint64_t*)h;
    *(uint64_t*)(lo + i) = *(uint64_t*)l;
}

// ---------------------------------------------------------------------------
// Tensor-core mixture GEMM via mma.sync (split-bf16, 3 passes, fp32 acc).
// z-batched: blockIdx.z selects A (via aStride), weight slot, and output.
// 512 threads / 16 warps: 4(M) x 4(N) warp grid, 32x32 warp tile, 3 stages.
// ---------------------------------------------------------------------------
__global__ __launch_bounds__(512)
void circuit_gemm_tc(const __nv_bfloat16* __restrict__ Ahi,  // base, + z*aStride
                     const __nv_bfloat16* __restrict__ Alo,
                     size_t aStride,
                     const __nv_bfloat16* __restrict__ WhiB,  // slot base
                     const __nv_bfloat16* __restrict__ WloB,
                     const float* __restrict__ wgt,           // [TOK, NEXP]
                     float* __restrict__ o0,
                     float* __restrict__ o1,
                     float* __restrict__ o2)
{
    extern __shared__ char smem[];
    __shared__ float swgt[128 * NEXP];
    const uint32_t sb = (uint32_t)__cvta_generic_to_shared(smem);
    int tid = threadIdx.x, lane = tid & 31, wid = tid >> 5;
    int bm = blockIdx.y * 128, bn = blockIdx.x * 128;
    int z  = blockIdx.z;
    const __nv_bfloat16* AhiZ = Ahi + (size_t)z * aStride;
    const __nv_bfloat16* AloZ = Alo + (size_t)z * aStride;
    const __nv_bfloat16* Whi  = WhiB + (size_t)z * WSZ;
    const __nv_bfloat16* Wlo  = WloB + (size_t)z * WSZ;
    float* out = (z == 0) ? o0 : (z == 1) ? o1 : o2;

    // ---- loader role: 4 threads per row, 16-k quarter each ----
    int r  = tid >> 2;                 // 0..127
    int kq = (tid & 3) * 16;           // k quarter
    const __nv_bfloat16* ahip = AhiZ + (size_t)(bm + r) * DIM + kq;
    const __nv_bfloat16* alop = AloZ + (size_t)(bm + r) * DIM + kq;
    const __nv_bfloat16* bhip = Whi + (size_t)(bn + r) * KTOT + kq;
    const __nv_bfloat16* blop = Wlo + (size_t)(bn + r) * KTOT + kq;
    const uint32_t rowoff = (uint32_t)(r * PAD + kq) * 2;

    auto load_chunk = [&](int c) {
        uint32_t st = sb + (uint32_t)(c % NSTAGE) * STAGE_BYTES;
        int k0 = c * BK;
        int d0 = k0 & (DIM - 1);
        #pragma unroll
        for (int ci = 0; ci < 2; ci++) {
            cp16(st + rowoff + ci * 16,                 ahip + d0 + ci * 8);
            cp16(st + MAT_BYTES + rowoff + ci * 16,     alop + d0 + ci * 8);
            cp16(st + 2 * MAT_BYTES + rowoff + ci * 16, bhip + k0 + ci * 8);
            cp16(st + 3 * MAT_BYTES + rowoff + ci * 16, blop + k0 + ci * 8);
        }
        cp_commit();
    };

    // ---- compute role: 4(M) x 4(N) warp grid, 32x32 warp tile ----
    int wm = (wid >> 2) * 32;
    int wn = (wid & 3) * 32;
    int arow = lane & 15;
    int acol = (lane >> 4) * 8;
    int q    = lane >> 3, rl = lane & 7;
    int brow = wn + ((q >= 2) ? 8 : 0) + rl;
    int bcol = (q & 1) * 8;
    const uint32_t aOff = (uint32_t)((wm + arow) * PAD + acol) * 2;
    const uint32_t bOff = (uint32_t)(2 * MAT_BYTES) + (uint32_t)(brow * PAD + bcol) * 2;
    int g = lane >> 2;

    float acc[2][4][4];
    float seg[2][4][4];
    #pragma unroll
    for (int i = 0; i < 2; i++)
        #pragma unroll
        for (int j = 0; j < 4; j++)
            #pragma unroll
            for (int e = 0; e < 4; e++) acc[i][j][e] = 0.f;

    // ---- prologue ----
    for (int idx = tid; idx < 128 * NEXP; idx += 512)
        swgt[idx] = wgt[(size_t)(bm + (idx >> 3)) * NEXP + (idx & 7)];
    load_chunk(0);
    load_chunk(1);

    int c = 0;
    for (int e = 0; e < NEXP; e++) {
        #pragma unroll
        for (int i = 0; i < 2; i++)
            #pragma unroll
            for (int j = 0; j < 4; j++)
                #pragma unroll
                for (int t = 0; t < 4; t++) seg[i][j][t] = 0.f;

        for (int dc = 0; dc < 16; dc++, c++) {
            if (c + 1 < NCHUNK) cp_wait<1>(); else cp_wait<0>();
            __syncthreads();
            if (c + 2 < NCHUNK) load_chunk(c + 2);

            uint32_t st = sb + (uint32_t)(c % NSTAGE) * STAGE_BYTES;
            uint32_t aHi = st + aOff;
            uint32_t bHi = st + bOff;

            #pragma unroll
            for (int ks = 0; ks < 4; ks++) {
                uint32_t kb = (uint32_t)(ks * 16) * 2;
                uint32_t bh[4][2], bl[4][2];
                #pragma unroll
                for (int p = 0; p < 2; p++) {
                    uint32_t ba = bHi + (uint32_t)(p * 16 * PAD) * 2 + kb;
                    LDSM4(bh[2*p][0], bh[2*p][1], bh[2*p+1][0], bh[2*p+1][1], ba);
                    LDSM4(bl[2*p][0], bl[2*p][1], bl[2*p+1][0], bl[2*p+1][1], ba + MAT_BYTES);
                }
                uint32_t ah[2][4], al[2][4];
                #pragma unroll
                for (int mt = 0; mt < 2; mt++) {
                    uint32_t aa = aHi + (uint32_t)(mt * 16 * PAD) * 2 + kb;
                    LDSM4(ah[mt][0], ah[mt][1], ah[mt][2], ah[mt][3], aa);
                    LDSM4(al[mt][0], al[mt][1], al[mt][2], al[mt][3], aa + MAT_BYTES);
                }
                // pass-major: 8 independent accumulators between same-acc reuse
                #pragma unroll
                for (int mt = 0; mt < 2; mt++)
                    #pragma unroll
                    for (int nt = 0; nt < 4; nt++)
                        mma_bf16(seg[mt][nt], ah[mt], bh[nt]);
                #pragma unroll
                for (int mt = 0; mt < 2; mt++)
                    #pragma unroll
                    for (int nt = 0; nt < 4; nt++)
                        mma_bf16(seg[mt][nt], ah[mt], bl[nt]);
                #pragma unroll
                for (int mt = 0; mt < 2; mt++)
                    #pragma unroll
                    for (int nt = 0; nt < 4; nt++)
                        mma_bf16(seg[mt][nt], al[mt], bh[nt]);
            }
        }

        // ---- expert boundary: acc += w(row, e) * seg ----
        #pragma unroll
        for (int mt = 0; mt < 2; mt++) {
            float w0 = swgt[(wm + mt * 16 + g) * NEXP + e];
            float w1 = swgt[(wm + mt * 16 + 8 + g) * NEXP + e];
            #pragma unroll
            for (int nt = 0; nt < 4; nt++) {
                acc[mt][nt][0] += w0 * seg[mt][nt][0];
                acc[mt][nt][1] += w0 * seg[mt][nt][1];
                acc[mt][nt][2] += w1 * seg[mt][nt][2];
                acc[mt][nt][3] += w1 * seg[mt][nt][3];
            }
        }
    }

    // ---- epilogue ----
    int tig = lane & 3;
    #pragma unroll
    for (int mt = 0; mt < 2; mt++) {
        #pragma unroll
        for (int nt = 0; nt < 4; nt++) {
            int row = bm + wm + mt * 16 + g;
            int col = bn + wn + nt * 8 + tig * 2;
            *(float2*)(out + (size_t)row * DIM + col) =
                make_float2(acc[mt][nt][0], acc[mt][nt][1]);
            *(float2*)(out + (size_t)(row + 8) * DIM + col) =
                make_float2(acc[mt][nt][2], acc[mt][nt][3]);
        }
    }
}

// ---------------------------------------------------------------------------
// Router: 48 logits per token (8 in / 32 proc / 8 out), softmax8 x2 + top-3
// ---------------------------------------------------------------------------
__global__ void router_kernel(const float* __restrict__ act,
                              const float* __restrict__ Wi,
                              const float* __restrict__ Wp,
                              const float* __restrict__ Wo,
                              float* __restrict__ inw,
                              int*   __restrict__ pidx,
                              float* __restrict__ outw)
{
    int t    = blockIdx.x;
    int tid  = threadIdx.x;
    int lane = tid & 31, warp = tid >> 5;
    __shared__ float xs[DIM];
    __shared__ float lg[48];

    const float* xr = act + (size_t)t * DIM;
    for (int i = tid; i < DIM; i += 128) xs[i] = xr[i];
    __syncthreads();

    for (int l = warp; l < 48; l += 4) {
        const float* wr = (l < 8) ? (Wi + (size_t)l * DIM)
                        : (l < 40) ? (Wp + (size_t)(l - 8) * DIM)
                                   : (Wo + (size_t)(l - 40) * DIM);
        float s = 0.f;
        for (int d = lane; d < DIM; d += 32) s += xs[d] * wr[d];
        #pragma unroll
        for (int off = 16; off > 0; off >>= 1)
            s += __shfl_xor_sync(0xffffffffu, s, off);
        if (lane == 0) lg[l] = s;
    }
    __syncthreads();

    if (tid == 0) {
        float m = lg[0];
        for (int i = 1; i < 8; i++) m = fmaxf(m, lg[i]);
        float e[8], sum = 0.f;
        for (int i = 0; i < 8; i++) { e[i] = expf(lg[i] - m); sum += e[i]; }
        for (int i = 0; i < 8; i++) inw[t * 8 + i] = e[i] / sum;

        bool used[NPROC];
        for (int n = 0; n < NPROC; n++) used[n] = false;
        for (int r = 0; r < TOPK; r++) {
            float best = -INFINITY; int bi = 0;
            for (int n = 0; n < NPROC; n++)
                if (!used[n] && lg[8 + n] > best) { best = lg[8 + n]; bi = n; }
            used[bi] = true;
            pidx[t * TOPK + r] = bi;
        }

        m = lg[40];
        for (int i = 1; i < 8; i++) m = fmaxf(m, lg[40 + i]);
        sum = 0.f;
        for (int i = 0; i < 8; i++) { e[i] = expf(lg[40 + i] - m); sum += e[i]; }
        for (int i = 0; i < 8; i++) outw[t * 8 + i] = e[i] / sum;
    }
}

// ---------------------------------------------------------------------------
// Householder reflections (z-batched): h -= 2 (h.v)/(v.v + 1e-8) v, 3x/token;
// writes split bf16 hi/lo output to slot z.
// ---------------------------------------------------------------------------
__global__ void householder_kernel(const float* __restrict__ hbase,
                                   const float* __restrict__ v0,
                                   const float* __restrict__ v1,
                                   const float* __restrict__ v2,
                                   const int* __restrict__ pidx,
                                   __nv_bfloat16* __restrict__ ohiB,
                                   __nv_bfloat16* __restrict__ oloB)
{
    int t = blockIdx.x, tid = threadIdx.x;
    int z = blockIdx.y;
    int lane = tid & 31, warp = tid >> 5;
    const float* vproc = (z == 0) ? v0 : (z == 1) ? v1 : v2;
    const float* hr = hbase + ((size_t)z * TOK + t) * DIM;
    __nv_bfloat16* ohi = ohiB + ((size_t)z * TOK + t) * DIM;
    __nv_bfloat16* olo = oloB + ((size_t)z * TOK + t) * DIM;

    float hv[4];
    #pragma unroll
    for (int i = 0; i < 4; i++) hv[i] = hr[tid + 256 * i];

    __shared__ float sred[16];

    for (int rfl = 0; rfl < TOPK; rfl++) {
        int idx = pidx[t * TOPK + rfl];
        const float* v = vproc + (size_t)idx * DIM;
        float vr[4];
        float d1 = 0.f, d2 = 0.f;
        #pragma unroll
        for (int i = 0; i < 4; i++) {
            vr[i] = v[tid + 256 * i];
            d1 += hv[i] * vr[i];
            d2 += vr[i] * vr[i];
        }
        #pragma unroll
        for (int off = 16; off > 0; off >>= 1) {
            d1 += __shfl_xor_sync(0xffffffffu, d1, off);
            d2 += __shfl_xor_sync(0xffffffffu, d2, off);
        }
        if (lane == 0) { sred[warp] = d1; sred[8 + warp] = d2; }
        __syncthreads();
        float t1 = 0.f, t2 = 0.f;
        #pragma unroll
        for (int w = 0; w < 8; w++) { t1 += sred[w]; t2 += sred[8 + w]; }
        float f = 2.f * t1 / (t2 + 1e-8f);
        #pragma unroll
        for (int i = 0; i < 4; i++) hv[i] -= f * vr[i];
        __syncthreads();
    }

    #pragma unroll
    for (int i = 0; i < 4; i++) {
        __nv_bfloat16 h, l;
        split_bf16(hv[i], h, l);
        ohi[tid + 256 * i] = h;
        olo[tid + 256 * i] = l;
    }
}

// ---------------------------------------------------------------------------
// Causal attention, online softmax (fp32). 16 q-rows per block (512 thr),
// lane-per-key within 32-key batches: one exp per lane per batch.
// ---------------------------------------------------------------------------
__global__ __launch_bounds__(512)
void attn_kernel(const float* __restrict__ Q,
                 const float* __restrict__ K,
                 const float* __restrict__ V,
                 float* __restrict__ O)
{
    const float scale = 0.08838834764831845f;  // 1/sqrt(128)
    int bh = blockIdx.y;
    int b = bh >> 3, hh = bh & 7;
    int q0 = blockIdx.x * 16;
    int tid = threadIdx.x, lane = tid & 31, warp = tid >> 5;

    const float* Qb = Q + (size_t)b * SEQ * DIM + hh * DHEAD;
    const float* Kb = K + (size_t)b * SEQ * DIM + hh * DHEAD;
    const float* Vb = V + (size_t)b * SEQ * DIM + hh * DHEAD;
    float*       Ob = O + (size_t)b * SEQ * DIM + hh * DHEAD;

    __shared__ float Ks[32][132];   // pad 132: conflict-free per-row float4
    __shared__ float Vs[32][132];
    __shared__ float qs[16][128];

    int qrow = q0 + warp;
    #pragma unroll
    for (int i = 0; i < 4; i++)
        qs[warp][lane + 32 * i] = Qb[(size_t)qrow * DIM + lane + 32 * i];

    float acc[4] = {0.f, 0.f, 0.f, 0.f};   // dims lane*4 .. lane*4+3
    float mi = -1e30f, li = 0.f;

    int kend = q0 + 16;   // need keys [0, kend)
    for (int c0 = 0; c0 < kend; c0 += 32) {
        __syncthreads();
        for (int idx = tid; idx < 32 * DHEAD; idx += 512) {
            int j = idx >> 7, d = idx & 127;
            Ks[j][d] = Kb[(size_t)(c0 + j) * DIM + d];
            Vs[j][d] = Vb[(size_t)(c0 + j) * DIM + d];
        }
        __syncthreads();

        int kg = c0 + lane;
        const float4* kr = (const float4*)&Ks[lane][0];
        const float4* qr = (const float4*)&qs[warp][0];
        float s = 0.f;
        #pragma unroll
        for (int w = 0; w < 32; w++) {
            float4 kk = kr[w];
            float4 qq = qr[w];
            s += qq.x * kk.x + qq.y * kk.y + qq.z * kk.z + qq.w * kk.w;
        }
        s *= scale;
        if (kg > qrow) s = -1e30f;   // causal mask (exp -> exact 0)

        float mb = s;
        #pragma unroll
        for (int off = 16; off > 0; off >>= 1)
            mb = fmaxf(mb, __shfl_xor_sync(0xffffffffu, mb, off));
        float mnew = fmaxf(mi, mb);
        float corr = expf(mi - mnew);
        float p = expf(s - mnew);
        float psum = p;
        #pragma unroll
        for (int off = 16; off > 0; off >>= 1)
            psum += __shfl_xor_sync(0xffffffffu, psum, off);
        li = li * corr + psum;

        #pragma unroll
        for (int i = 0; i < 4; i++) acc[i] *= corr;
        #pragma unroll
        for (int j = 0; j < 32; j++) {
            float pj = __shfl_sync(0xffffffffu, p, j);
            float4 vv = *(const float4*)&Vs[j][lane * 4];
            acc[0] += pj * vv.x;
            acc[1] += pj * vv.y;
            acc[2] += pj * vv.z;
            acc[3] += pj * vv.w;
        }
        mi = mnew;
    }

    float inv = 1.f / li;
    float4 o4 = make_float4(acc[0] * inv, acc[1] * inv, acc[2] * inv, acc[3] * inv);
    *(float4*)(Ob + (size_t)qrow * DIM + lane * 4) = o4;
}

// ---------------------------------------------------------------------------
// Launch
// ---------------------------------------------------------------------------
extern "C" void kernel_launch(void* const* d_in, const int* in_sizes, int n_in,
                              void* d_out, int out_size)
{
    const float* x       = (const float*)d_in[0];
    const float* Wr_in   = (const float*)d_in[2];
    const float* Wr_proc = (const float*)d_in[3];
    const float* Wr_out  = (const float*)d_in[4];
    const float* WrO_in  = (const float*)d_in[5];
    const float* WrO_proc= (const float*)d_in[6];
    const float* WrO_out = (const float*)d_in[7];
    const float* Wq_in   = (const float*)d_in[8];
    const float* vq      = (const float*)d_in[9];
    const float* Wq_out  = (const float*)d_in[10];
    const float* Wk_in   = (const float*)d_in[11];
    const float* vk      = (const float*)d_in[12];
    const float* Wk_out  = (const float*)d_in[13];
    const float* Wv_in   = (const float*)d_in[14];
    const float* vv      = (const float*)d_in[15];
    const float* Wv_out  = (const float*)d_in[16];
    const float* Wo_in   = (const float*)d_in[17];
    const float* vo      = (const float*)d_in[18];
    const float* Wo_out  = (const float*)d_in[19];
    float* out = (float*)d_out;

    float *h, *Q, *Kc, *V, *O, *inw, *outw;
    int* pidx;
    __nv_bfloat16 *whi, *wlo, *xhi, *xlo, *hhi, *hlo;
    cudaGetSymbolAddress((void**)&h,    g_h);
    cudaGetSymbolAddress((void**)&Q,    g_Q);
    cudaGetSymbolAddress((void**)&Kc,   g_Kc);
    cudaGetSymbolAddress((void**)&V,    g_V);
    cudaGetSymbolAddress((void**)&O,    g_O);
    cudaGetSymbolAddress((void**)&inw,  g_inw);
    cudaGetSymbolAddress((void**)&outw, g_outw);
    cudaGetSymbolAddress((void**)&pidx, g_pidx);
    cudaGetSymbolAddress((void**)&whi,  g_whi);
    cudaGetSymbolAddress((void**)&wlo,  g_wlo);
    cudaGetSymbolAddress((void**)&xhi,  g_xhi);
    cudaGetSymbolAddress((void**)&xlo,  g_xlo);
    cudaGetSymbolAddress((void**)&hhi,  g_hhi);
    cudaGetSymbolAddress((void**)&hlo,  g_hlo);

    cudaFuncSetAttribute(circuit_gemm_tc,
                         cudaFuncAttributeMaxDynamicSharedMemorySize,
                         SMEM_GEMM_BYTES);

    dim3 gGemm3(DIM / 128, TOK / 128, 3);   // 768 CTAs
    dim3 gGemm1(DIM / 128, TOK / 128, 1);   // 256 CTAs
    dim3 gPrep3(DIM / 32, KTOT / 32, 3);
    dim3 gPrep1(DIM / 32, KTOT / 32, 1);
    int  gSplit = TOK * DIM / (256 * 4);    // 4096

    // ---- Router on x + x split ----
    router_kernel<<<TOK, 128>>>(x, Wr_in, Wr_proc, Wr_out, inw, pidx, outw);
    split_kernel<<<gSplit, 256>>>(x, xhi, xlo);

    // ---- Q/K/V in-projections (fused) ----
    prep_w_kernel<<<gPrep3, 256>>>(Wq_in, Wk_in, Wv_in, whi, wlo);
    circuit_gemm_tc<<<gGemm3, 512, SMEM_GEMM_BYTES>>>(
        xhi, xlo, 0, whi, wlo, inw, h, h + ASZ, h + 2 * ASZ);

    // ---- Householders (fused) ----
    householder_kernel<<<dim3(TOK, 3), 256>>>(h, vq, vk, vv, pidx, hhi, hlo);

    // ---- Q/K/V out-projections (fused) ----
    prep_w_kernel<<<gPrep3, 256>>>(Wq_out, Wk_out, Wv_out, whi, wlo);
    circuit_gemm_tc<<<gGemm3, 512, SMEM_GEMM_BYTES>>>(
        hhi, hlo, ASZ, whi, wlo, outw, Q, Kc, V);

    // ---- Attention ----
    attn_kernel<<<dim3(SEQ / 16, NBATCH * NH), 512>>>(Q, Kc, V, O);

    // ---- Router on O + output circuit ----
    router_kernel<<<TOK, 128>>>(O, WrO_in, WrO_proc, WrO_out, inw, pidx, outw);
    split_kernel<<<gSplit, 256>>>(O, xhi, xlo);
    prep_w_kernel<<<gPrep1, 256>>>(Wo_in, Wo_in, Wo_in, whi, wlo);
    circuit_gemm_tc<<<gGemm1, 512, SMEM_GEMM_BYTES>>>(
        xhi, xlo, 0, whi, wlo, inw, h, h, h);
    householder_kernel<<<dim3(TOK, 1), 256>>>(h, vo, vo, vo, pidx, hhi, hlo);
    prep_w_kernel<<<gPrep1, 256>>>(Wo_out, Wo_out, Wo_out, whi, wlo);
    circuit_gemm_tc<<<gGemm1, 512, SMEM_GEMM_BYTES>>>(
        hhi, hlo, 0, whi, wlo, outw, out, out, out);

    (void)in_sizes; (void)n_in; (void)out_size;
}

// round 12
// speedup vs baseline: 1.4263x; 1.2540x over previous
#include <cuda_runtime.h>
#include <cuda_fp16.h>
#include <math.h>
#include <stdint.h>

// Problem constants
#define TOK   4096      // B*S
#define DIM   1024      // D == R
#define SEQ   2048
#define NBATCH 2
#define NH    8
#define DHEAD 128
#define NEXP  8
#define NPROC 32
#define TOPK  3
#define KTOT  8192      // NEXP * DIM
#define WSZ   ((size_t)DIM * KTOT)   // elements per weight slot
#define ASZ   ((size_t)TOK * DIM)

// GEMM tiling: 128x128xBK64, 512 threads, 3 stages, fp16 2-pass
#define BK      64
#define NCHUNK  (KTOT / BK)           // 128
#define PAD     72                    // smem row stride in fp16 halves (144B)
#define MAT_BYTES   (128 * PAD * 2)   // 18432 per matrix
#define STAGE_BYTES (3 * MAT_BYTES)   // A, Bhi, Blo
#define NSTAGE  3
#define SMEM_GEMM_BYTES (NSTAGE * STAGE_BYTES)   // 165888

// ---------------------------------------------------------------------------
// Scratch (device globals — no runtime allocation allowed)
// ---------------------------------------------------------------------------
__device__ float g_h  [3 * TOK * DIM];
__device__ float g_Q  [TOK * DIM];
__device__ float g_Kc [TOK * DIM];
__device__ float g_V  [TOK * DIM];
__device__ float g_O  [TOK * DIM];
__device__ float g_inw [TOK * NEXP];
__device__ float g_outw[TOK * NEXP];
__device__ int   g_pidx[TOK * TOPK];
__device__ __half g_whi[3 * DIM * KTOT];   // weightT hi, 3 slots [N=1024, K=8192]
__device__ __half g_wlo[3 * DIM * KTOT];
__device__ __half g_xh [TOK * DIM];        // activation fp16 (x / O)
__device__ __half g_hh [3 * TOK * DIM];    // householder output fp16

// ---------------------------------------------------------------------------
// Portable tensor-core helpers (sm_80+ PTX; no 'a'-suffix features)
// ---------------------------------------------------------------------------
#define LDSM4(r0, r1, r2, r3, addr) \
    asm volatile("ldmatrix.sync.aligned.m8n8.x4.shared.b16 {%0,%1,%2,%3}, [%4];" \
                 : "=r"(r0), "=r"(r1), "=r"(r2), "=r"(r3) : "r"(addr))

__device__ __forceinline__ void mma_f16(float* c, const uint32_t* a, const uint32_t* b) {
    asm volatile(
        "mma.sync.aligned.m16n8k16.row.col.f32.f16.f16.f32 "
        "{%0,%1,%2,%3}, {%4,%5,%6,%7}, {%8,%9}, {%0,%1,%2,%3};"
        : "+f"(c[0]), "+f"(c[1]), "+f"(c[2]), "+f"(c[3])
        : "r"(a[0]), "r"(a[1]), "r"(a[2]), "r"(a[3]), "r"(b[0]), "r"(b[1]));
}

__device__ __forceinline__ void cp16(uint32_t saddr, const void* gaddr) {
    asm volatile("cp.async.cg.shared.global [%0], [%1], 16;" :: "r"(saddr), "l"(gaddr));
}
__device__ __forceinline__ void cp_commit() {
    asm volatile("cp.async.commit_group;" ::: "memory");
}
template <int N>
__device__ __forceinline__ void cp_wait() {
    asm volatile("cp.async.wait_group %0;" :: "n"(N) : "memory");
}

__device__ __forceinline__ void split_f16(float v, __half& hi, __half& lo) {
    hi = __float2half_rn(v);
    lo = __float2half_rn(v - __half2float(hi));
}

// ---------------------------------------------------------------------------
// Weight prep (z-batched): W_z[KTOT, DIM] fp32 -> fp16 hi/lo [DIM, KTOT] slot z
// ---------------------------------------------------------------------------
__global__ void prep_w_kernel(const float* __restrict__ W0,
                              const float* __restrict__ W1,
                              const float* __restrict__ W2,
                              __half* __restrict__ Whi,
                              __half* __restrict__ Wlo)
{
    int z = blockIdx.z;
    const float* W = (z == 0) ? W0 : (z == 1) ? W1 : W2;
    __half* whi = Whi + (size_t)z * WSZ;
    __half* wlo = Wlo + (size_t)z * WSZ;

    __shared__ float ts[32][33];
    int k0 = blockIdx.y * 32, n0 = blockIdx.x * 32;
    int tx = threadIdx.x & 31, ty = threadIdx.x >> 5;   // 32 x 8
    #pragma unroll
    for (int r = 0; r < 4; r++) {
        int k = ty + r * 8;
        ts[k][tx] = W[(size_t)(k0 + k) * DIM + n0 + tx];
    }
    __syncthreads();
    #pragma unroll
    for (int r = 0; r < 4; r++) {
        int n = ty + r * 8;
        float v = ts[tx][n];                      // W[k0+tx][n0+n]
        __half h, l;
        split_f16(v, h, l);
        size_t o = (size_t)(n0 + n) * KTOT + k0 + tx;
        whi[o] = h;
        wlo[o] = l;
    }
}

// ---------------------------------------------------------------------------
// Activation convert: fp32 [TOK,DIM] -> fp16
// ---------------------------------------------------------------------------
__global__ void split_kernel(const float* __restrict__ src,
                             __half* __restrict__ dst)
{
    int i = (blockIdx.x * 256 + threadIdx.x) * 4;
    float4 v = *(const float4*)(src + i);
    __half h[4];
    h[0] = __float2half_rn(v.x);
    h[1] = __float2half_rn(v.y);
    h[2] = __float2half_rn(v.z);
    h[3] = __float2half_rn(v.w);
    *(uint64_t*)(dst + i) = *(uint64_t*)h;
}

// ---------------------------------------------------------------------------
// Tensor-core mixture GEMM via mma.sync (fp16 A + hi/lo B, 2 passes, fp32 acc).
// z-batched: blockIdx.z selects A (via aStride), weight slot, and output.
// 512 threads / 16 warps: 4(M) x 4(N) warp grid, 32x32 warp tile, 3 stages.
// ---------------------------------------------------------------------------
__global__ __launch_bounds__(512)
void circuit_gemm_tc(const __half* __restrict__ A,      // base, + z*aStride
                     size_t aStride,
                     const __half* __restrict__ WhiB,   // slot base
                     const __half* __restrict__ WloB,
                     const float* __restrict__ wgt,     // [TOK, NEXP]
                     float* __restrict__ o0,
                     float* __restrict__ o1,
                     float* __restrict__ o2)
{
    extern __shared__ char smem[];
    __shared__ float swgt[128 * NEXP];
    const uint32_t sb = (uint32_t)__cvta_generic_to_shared(smem);
    int tid = threadIdx.x, lane = tid & 31, wid = tid >> 5;
    int bm = blockIdx.y * 128, bn = blockIdx.x * 128;
    int z  = blockIdx.z;
    const __half* AZ  = A + (size_t)z * aStride;
    const __half* Whi = WhiB + (size_t)z * WSZ;
    const __half* Wlo = WloB + (size_t)z * WSZ;
    float* out = (z == 0) ? o0 : (z == 1) ? o1 : o2;

    // ---- loader role: 4 threads per row, 16-k quarter each ----
    int r  = tid >> 2;                 // 0..127
    int kq = (tid & 3) * 16;           // k quarter
    const __half* ap   = AZ  + (size_t)(bm + r) * DIM + kq;
    const __half* bhip = Whi + (size_t)(bn + r) * KTOT + kq;
    const __half* blop = Wlo + (size_t)(bn + r) * KTOT + kq;
    const uint32_t rowoff = (uint32_t)(r * PAD + kq) * 2;

    auto load_chunk = [&](int c) {
        uint32_t st = sb + (uint32_t)(c % NSTAGE) * STAGE_BYTES;
        int k0 = c * BK;
        int d0 = k0 & (DIM - 1);
        #pragma unroll
        for (int ci = 0; ci < 2; ci++) {
            cp16(st + rowoff + ci * 16,                 ap   + d0 + ci * 8);
            cp16(st + MAT_BYTES + rowoff + ci * 16,     bhip + k0 + ci * 8);
            cp16(st + 2 * MAT_BYTES + rowoff + ci * 16, blop + k0 + ci * 8);
        }
        cp_commit();
    };

    // ---- compute role: 4(M) x 4(N) warp grid, 32x32 warp tile ----
    int wm = (wid >> 2) * 32;
    int wn = (wid & 3) * 32;
    int arow = lane & 15;
    int acol = (lane >> 4) * 8;
    int q    = lane >> 3, rl = lane & 7;
    int brow = wn + ((q >= 2) ? 8 : 0) + rl;
    int bcol = (q & 1) * 8;
    const uint32_t aOff = (uint32_t)((wm + arow) * PAD + acol) * 2;
    const uint32_t bOff = (uint32_t)MAT_BYTES + (uint32_t)(brow * PAD + bcol) * 2;
    int g = lane >> 2;

    float acc[2][4][4];
    float seg[2][4][4];
    #pragma unroll
    for (int i = 0; i < 2; i++)
        #pragma unroll
        for (int j = 0; j < 4; j++)
            #pragma unroll
            for (int e = 0; e < 4; e++) acc[i][j][e] = 0.f;

    // ---- prologue ----
    for (int idx = tid; idx < 128 * NEXP; idx += 512)
        swgt[idx] = wgt[(size_t)(bm + (idx >> 3)) * NEXP + (idx & 7)];
    load_chunk(0);
    load_chunk(1);

    int c = 0;
    for (int e = 0; e < NEXP; e++) {
        #pragma unroll
        for (int i = 0; i < 2; i++)
            #pragma unroll
            for (int j = 0; j < 4; j++)
                #pragma unroll
                for (int t = 0; t < 4; t++) seg[i][j][t] = 0.f;

        for (int dc = 0; dc < 16; dc++, c++) {
            if (c + 1 < NCHUNK) cp_wait<1>(); else cp_wait<0>();
            __syncthreads();
            if (c + 2 < NCHUNK) load_chunk(c + 2);

            uint32_t st = sb + (uint32_t)(c % NSTAGE) * STAGE_BYTES;
            uint32_t aHi = st + aOff;
            uint32_t bHi = st + bOff;

            #pragma unroll
            for (int ks = 0; ks < 4; ks++) {
                uint32_t kb = (uint32_t)(ks * 16) * 2;
                uint32_t bh[4][2], bl[4][2];
                #pragma unroll
                for (int p = 0; p < 2; p++) {
                    uint32_t ba = bHi + (uint32_t)(p * 16 * PAD) * 2 + kb;
                    LDSM4(bh[2*p][0], bh[2*p][1], bh[2*p+1][0], bh[2*p+1][1], ba);
                    LDSM4(bl[2*p][0], bl[2*p][1], bl[2*p+1][0], bl[2*p+1][1], ba + MAT_BYTES);
                }
                uint32_t ah[2][4];
                #pragma unroll
                for (int mt = 0; mt < 2; mt++) {
                    uint32_t aa = aHi + (uint32_t)(mt * 16 * PAD) * 2 + kb;
                    LDSM4(ah[mt][0], ah[mt][1], ah[mt][2], ah[mt][3], aa);
                }
                // pass-major: 8 independent accumulators between same-acc reuse
                #pragma unroll
                for (int mt = 0; mt < 2; mt++)
                    #pragma unroll
                    for (int nt = 0; nt < 4; nt++)
                        mma_f16(seg[mt][nt], ah[mt], bh[nt]);
                #pragma unroll
                for (int mt = 0; mt < 2; mt++)
                    #pragma unroll
                    for (int nt = 0; nt < 4; nt++)
                        mma_f16(seg[mt][nt], ah[mt], bl[nt]);
            }
        }

        // ---- expert boundary: acc += w(row, e) * seg ----
        #pragma unroll
        for (int mt = 0; mt < 2; mt++) {
            float w0 = swgt[(wm + mt * 16 + g) * NEXP + e];
            float w1 = swgt[(wm + mt * 16 + 8 + g) * NEXP + e];
            #pragma unroll
            for (int nt = 0; nt < 4; nt++) {
                acc[mt][nt][0] += w0 * seg[mt][nt][0];
                acc[mt][nt][1] += w0 * seg[mt][nt][1];
                acc[mt][nt][2] += w1 * seg[mt][nt][2];
                acc[mt][nt][3] += w1 * seg[mt][nt][3];
            }
        }
    }

    // ---- epilogue ----
    int tig = lane & 3;
    #pragma unroll
    for (int mt = 0; mt < 2; mt++) {
        #pragma unroll
        for (int nt = 0; nt < 4; nt++) {
            int row = bm + wm + mt * 16 + g;
            int col = bn + wn + nt * 8 + tig * 2;
            *(float2*)(out + (size_t)row * DIM + col) =
                make_float2(acc[mt][nt][0], acc[mt][nt][1]);
            *(float2*)(out + (size_t)(row + 8) * DIM + col) =
                make_float2(acc[mt][nt][2], acc[mt][nt][3]);
        }
    }
}

// ---------------------------------------------------------------------------
// Router: 48 logits per token (8 in / 32 proc / 8 out), softmax8 x2 + top-3
// ---------------------------------------------------------------------------
__global__ void router_kernel(const float* __restrict__ act,
                              const float* __restrict__ Wi,
                              const float* __restrict__ Wp,
                              const float* __restrict__ Wo,
                              float* __restrict__ inw,
                              int*   __restrict__ pidx,
                              float* __restrict__ outw)
{
    int t    = blockIdx.x;
    int tid  = threadIdx.x;
    int lane = tid & 31, warp = tid >> 5;
    __shared__ float xs[DIM];
    __shared__ float lg[48];

    const float* xr = act + (size_t)t * DIM;
    for (int i = tid; i < DIM; i += 128) xs[i] = xr[i];
    __syncthreads();

    for (int l = warp; l < 48; l += 4) {
        const float* wr = (l < 8) ? (Wi + (size_t)l * DIM)
                        : (l < 40) ? (Wp + (size_t)(l - 8) * DIM)
                                   : (Wo + (size_t)(l - 40) * DIM);
        float s = 0.f;
        for (int d = lane; d < DIM; d += 32) s += xs[d] * wr[d];
        #pragma unroll
        for (int off = 16; off > 0; off >>= 1)
            s += __shfl_xor_sync(0xffffffffu, s, off);
        if (lane == 0) lg[l] = s;
    }
    __syncthreads();

    if (tid == 0) {
        float m = lg[0];
        for (int i = 1; i < 8; i++) m = fmaxf(m, lg[i]);
        float e[8], sum = 0.f;
        for (int i = 0; i < 8; i++) { e[i] = expf(lg[i] - m); sum += e[i]; }
        for (int i = 0; i < 8; i++) inw[t * 8 + i] = e[i] / sum;

        bool used[NPROC];
        for (int n = 0; n < NPROC; n++) used[n] = false;
        for (int r = 0; r < TOPK; r++) {
            float best = -INFINITY; int bi = 0;
            for (int n = 0; n < NPROC; n++)
                if (!used[n] && lg[8 + n] > best) { best = lg[8 + n]; bi = n; }
            used[bi] = true;
            pidx[t * TOPK + r] = bi;
        }

        m = lg[40];
        for (int i = 1; i < 8; i++) m = fmaxf(m, lg[40 + i]);
        sum = 0.f;
        for (int i = 0; i < 8; i++) { e[i] = expf(lg[40 + i] - m); sum += e[i]; }
        for (int i = 0; i < 8; i++) outw[t * 8 + i] = e[i] / sum;
    }
}

// ---------------------------------------------------------------------------
// Householder reflections (z-batched): h -= 2 (h.v)/(v.v + 1e-8) v, 3x/token;
// writes fp16 output to slot z.
// ---------------------------------------------------------------------------
__global__ void householder_kernel(const float* __restrict__ hbase,
                                   const float* __restrict__ v0,
                                   const float* __restrict__ v1,
                                   const float* __restrict__ v2,
                                   const int* __restrict__ pidx,
                                   __half* __restrict__ outB)
{
    int t = blockIdx.x, tid = threadIdx.x;
    int z = blockIdx.y;
    int lane = tid & 31, warp = tid >> 5;
    const float* vproc = (z == 0) ? v0 : (z == 1) ? v1 : v2;
    const float* hr = hbase + ((size_t)z * TOK + t) * DIM;
    __half* oh = outB + ((size_t)z * TOK + t) * DIM;

    float hv[4];
    #pragma unroll
    for (int i = 0; i < 4; i++) hv[i] = hr[tid + 256 * i];

    __shared__ float sred[16];

    for (int rfl = 0; rfl < TOPK; rfl++) {
        int idx = pidx[t * TOPK + rfl];
        const float* v = vproc + (size_t)idx * DIM;
        float vr[4];
        float d1 = 0.f, d2 = 0.f;
        #pragma unroll
        for (int i = 0; i < 4; i++) {
            vr[i] = v[tid + 256 * i];
            d1 += hv[i] * vr[i];
            d2 += vr[i] * vr[i];
        }
        #pragma unroll
        for (int off = 16; off > 0; off >>= 1) {
            d1 += __shfl_xor_sync(0xffffffffu, d1, off);
            d2 += __shfl_xor_sync(0xffffffffu, d2, off);
        }
        if (lane == 0) { sred[warp] = d1; sred[8 + warp] = d2; }
        __syncthreads();
        float t1 = 0.f, t2 = 0.f;
        #pragma unroll
        for (int w = 0; w < 8; w++) { t1 += sred[w]; t2 += sred[8 + w]; }
        float f = 2.f * t1 / (t2 + 1e-8f);
        #pragma unroll
        for (int i = 0; i < 4; i++) hv[i] -= f * vr[i];
        __syncthreads();
    }

    #pragma unroll
    for (int i = 0; i < 4; i++)
        oh[tid + 256 * i] = __float2half_rn(hv[i]);
}

// ---------------------------------------------------------------------------
// Causal attention, online softmax (fp32). 16 q-rows per block (512 thr),
// lane-per-key within 32-key batches: one exp per lane per batch.
// ---------------------------------------------------------------------------
__global__ __launch_bounds__(512)
void attn_kernel(const float* __restrict__ Q,
                 const float* __restrict__ K,
                 const float* __restrict__ V,
                 float* __restrict__ O)
{
    const float scale = 0.08838834764831845f;  // 1/sqrt(128)
    int bh = blockIdx.y;
    int b = bh >> 3, hh = bh & 7;
    int q0 = blockIdx.x * 16;
    int tid = threadIdx.x, lane = tid & 31, warp = tid >> 5;

    const float* Qb = Q + (size_t)b * SEQ * DIM + hh * DHEAD;
    const float* Kb = K + (size_t)b * SEQ * DIM + hh * DHEAD;
    const float* Vb = V + (size_t)b * SEQ * DIM + hh * DHEAD;
    float*       Ob = O + (size_t)b * SEQ * DIM + hh * DHEAD;

    __shared__ float Ks[32][132];   // pad 132: conflict-free per-row float4
    __shared__ float Vs[32][132];
    __shared__ float qs[16][128];

    int qrow = q0 + warp;
    #pragma unroll
    for (int i = 0; i < 4; i++)
        qs[warp][lane + 32 * i] = Qb[(size_t)qrow * DIM + lane + 32 * i];

    float acc[4] = {0.f, 0.f, 0.f, 0.f};   // dims lane*4 .. lane*4+3
    float mi = -1e30f, li = 0.f;

    int kend = q0 + 16;   // need keys [0, kend)
    for (int c0 = 0; c0 < kend; c0 += 32) {
        __syncthreads();
        for (int idx = tid; idx < 32 * DHEAD; idx += 512) {
            int j = idx >> 7, d = idx & 127;
            Ks[j][d] = Kb[(size_t)(c0 + j) * DIM + d];
            Vs[j][d] = Vb[(size_t)(c0 + j) * DIM + d];
        }
        __syncthreads();

        int kg = c0 + lane;
        const float4* kr = (const float4*)&Ks[lane][0];
        const float4* qr = (const float4*)&qs[warp][0];
        float s = 0.f;
        #pragma unroll
        for (int w = 0; w < 32; w++) {
            float4 kk = kr[w];
            float4 qq = qr[w];
            s += qq.x * kk.x + qq.y * kk.y + qq.z * kk.z + qq.w * kk.w;
        }
        s *= scale;
        if (kg > qrow) s = -1e30f;   // causal mask (exp -> exact 0)

        float mb = s;
        #pragma unroll
        for (int off = 16; off > 0; off >>= 1)
            mb = fmaxf(mb, __shfl_xor_sync(0xffffffffu, mb, off));
        float mnew = fmaxf(mi, mb);
        float corr = expf(mi - mnew);
        float p = expf(s - mnew);
        float psum = p;
        #pragma unroll
        for (int off = 16; off > 0; off >>= 1)
            psum += __shfl_xor_sync(0xffffffffu, psum, off);
        li = li * corr + psum;

        #pragma unroll
        for (int i = 0; i < 4; i++) acc[i] *= corr;
        #pragma unroll
        for (int j = 0; j < 32; j++) {
            float pj = __shfl_sync(0xffffffffu, p, j);
            float4 vv = *(const float4*)&Vs[j][lane * 4];
            acc[0] += pj * vv.x;
            acc[1] += pj * vv.y;
            acc[2] += pj * vv.z;
            acc[3] += pj * vv.w;
        }
        mi = mnew;
    }

    float inv = 1.f / li;
    float4 o4 = make_float4(acc[0] * inv, acc[1] * inv, acc[2] * inv, acc[3] * inv);
    *(float4*)(Ob + (size_t)qrow * DIM + lane * 4) = o4;
}

// ---------------------------------------------------------------------------
// Launch
// ---------------------------------------------------------------------------
extern "C" void kernel_launch(void* const* d_in, const int* in_sizes, int n_in,
                              void* d_out, int out_size)
{
    const float* x       = (const float*)d_in[0];
    const float* Wr_in   = (const float*)d_in[2];
    const float* Wr_proc = (const float*)d_in[3];
    const float* Wr_out  = (const float*)d_in[4];
    const float* WrO_in  = (const float*)d_in[5];
    const float* WrO_proc= (const float*)d_in[6];
    const float* WrO_out = (const float*)d_in[7];
    const float* Wq_in   = (const float*)d_in[8];
    const float* vq      = (const float*)d_in[9];
    const float* Wq_out  = (const float*)d_in[10];
    const float* Wk_in   = (const float*)d_in[11];
    const float* vk      = (const float*)d_in[12];
    const float* Wk_out  = (const float*)d_in[13];
    const float* Wv_in   = (const float*)d_in[14];
    const float* vv      = (const float*)d_in[15];
    const float* Wv_out  = (const float*)d_in[16];
    const float* Wo_in   = (const float*)d_in[17];
    const float* vo      = (const float*)d_in[18];
    const float* Wo_out  = (const float*)d_in[19];
    float* out = (float*)d_out;

    float *h, *Q, *Kc, *V, *O, *inw, *outw;
    int* pidx;
    __half *whi, *wlo, *xh, *hh;
    cudaGetSymbolAddress((void**)&h,    g_h);
    cudaGetSymbolAddress((void**)&Q,    g_Q);
    cudaGetSymbolAddress((void**)&Kc,   g_Kc);
    cudaGetSymbolAddress((void**)&V,    g_V);
    cudaGetSymbolAddress((void**)&O,    g_O);
    cudaGetSymbolAddress((void**)&inw,  g_inw);
    cudaGetSymbolAddress((void**)&outw, g_outw);
    cudaGetSymbolAddress((void**)&pidx, g_pidx);
    cudaGetSymbolAddress((void**)&whi,  g_whi);
    cudaGetSymbolAddress((void**)&wlo,  g_wlo);
    cudaGetSymbolAddress((void**)&xh,   g_xh);
    cudaGetSymbolAddress((void**)&hh,   g_hh);

    cudaFuncSetAttribute(circuit_gemm_tc,
                         cudaFuncAttributeMaxDynamicSharedMemorySize,
                         SMEM_GEMM_BYTES);

    dim3 gGemm3(DIM / 128, TOK / 128, 3);   // 768 CTAs
    dim3 gGemm1(DIM / 128, TOK / 128, 1);   // 256 CTAs
    dim3 gPrep3(DIM / 32, KTOT / 32, 3);
    dim3 gPrep1(DIM / 32, KTOT / 32, 1);
    int  gSplit = TOK * DIM / (256 * 4);    // 4096

    // ---- Router on x + x convert ----
    router_kernel<<<TOK, 128>>>(x, Wr_in, Wr_proc, Wr_out, inw, pidx, outw);
    split_kernel<<<gSplit, 256>>>(x, xh);

    // ---- Q/K/V in-projections (fused) ----
    prep_w_kernel<<<gPrep3, 256>>>(Wq_in, Wk_in, Wv_in, whi, wlo);
    circuit_gemm_tc<<<gGemm3, 512, SMEM_GEMM_BYTES>>>(
        xh, 0, whi, wlo, inw, h, h + ASZ, h + 2 * ASZ);

    // ---- Householders (fused) ----
    householder_kernel<<<dim3(TOK, 3), 256>>>(h, vq, vk, vv, pidx, hh);

    // ---- Q/K/V out-projections (fused) ----
    prep_w_kernel<<<gPrep3, 256>>>(Wq_out, Wk_out, Wv_out, whi, wlo);
    circuit_gemm_tc<<<gGemm3, 512, SMEM_GEMM_BYTES>>>(
        hh, ASZ, whi, wlo, outw, Q, Kc, V);

    // ---- Attention ----
    attn_kernel<<<dim3(SEQ / 16, NBATCH * NH), 512>>>(Q, Kc, V, O);

    // ---- Router on O + output circuit ----
    router_kernel<<<TOK, 128>>>(O, WrO_in, WrO_proc, WrO_out, inw, pidx, outw);
    split_kernel<<<gSplit, 256>>>(O, xh);
    prep_w_kernel<<<gPrep1, 256>>>(Wo_in, Wo_in, Wo_in, whi, wlo);
    circuit_gemm_tc<<<gGemm1, 512, SMEM_GEMM_BYTES>>>(
        xh, 0, whi, wlo, inw, h, h, h);
    householder_kernel<<<dim3(TOK, 1), 256>>>(h, vo, vo, vo, pidx, hh);
    prep_w_kernel<<<gPrep1, 256>>>(Wo_out, Wo_out, Wo_out, whi, wlo);
    circuit_gemm_tc<<<gGemm1, 512, SMEM_GEMM_BYTES>>>(
        hh, 0, whi, wlo, outw, out, out, out);

    (void)in_sizes; (void)n_in; (void)out_size;
}

// round 14
// speedup vs baseline: 1.5632x; 1.0960x over previous
#include <cuda_runtime.h>
#include <cuda_fp16.h>
#include <math.h>
#include <stdint.h>

// Problem constants
#define TOK   4096      // B*S
#define DIM   1024      // D == R
#define SEQ   2048
#define NBATCH 2
#define NH    8
#define DHEAD 128
#define NEXP  8
#define NPROC 32
#define TOPK  3
#define KTOT  8192      // NEXP * DIM
#define WSZ   ((size_t)DIM * KTOT)   // elements per weight slot
#define ASZ   ((size_t)TOK * DIM)

// GEMM tiling: 128x128xBK64, 512 threads, 3 stages, fp16 2-pass
#define BK      64
#define NCHUNK  (KTOT / BK)           // 128
#define PAD     72                    // smem row stride in fp16 halves (144B)
#define MAT_BYTES   (128 * PAD * 2)   // 18432 per matrix
#define STAGE_BYTES (3 * MAT_BYTES)   // A, Bhi, Blo
#define NSTAGE  3
#define SMEM_GEMM_BYTES (NSTAGE * STAGE_BYTES)   // 165888

// Attention smem layout (dynamic): Ks[32][132] | Vs[32][132] | qs[32][128]
#define KS_STRIDE 132
#define QS_STRIDE 128
#define ATTN_KS_OFF 0
#define ATTN_VS_OFF (32 * KS_STRIDE)
#define ATTN_QS_OFF (2 * 32 * KS_STRIDE)
#define SMEM_ATTN_BYTES ((2 * 32 * KS_STRIDE + 32 * QS_STRIDE) * 4)   // 50176

// ---------------------------------------------------------------------------
// Scratch (device globals — no runtime allocation allowed)
// ---------------------------------------------------------------------------
__device__ float g_h  [3 * TOK * DIM];
__device__ float g_Q  [TOK * DIM];
__device__ float g_Kc [TOK * DIM];
__device__ float g_V  [TOK * DIM];
__device__ float g_O  [TOK * DIM];
__device__ float g_inw [TOK * NEXP];
__device__ float g_outw[TOK * NEXP];
__device__ int   g_pidx[TOK * TOPK];
__device__ __half g_whi[3 * DIM * KTOT];   // weightT hi, 3 slots [N=1024, K=8192]
__device__ __half g_wlo[3 * DIM * KTOT];
__device__ __half g_xh [TOK * DIM];        // activation fp16 (x / O)
__device__ __half g_hh [3 * TOK * DIM];    // householder output fp16

// ---------------------------------------------------------------------------
// Portable tensor-core helpers (sm_80+ PTX; no 'a'-suffix features)
// ---------------------------------------------------------------------------
#define LDSM4(r0, r1, r2, r3, addr) \
    asm volatile("ldmatrix.sync.aligned.m8n8.x4.shared.b16 {%0,%1,%2,%3}, [%4];" \
                 : "=r"(r0), "=r"(r1), "=r"(r2), "=r"(r3) : "r"(addr))

__device__ __forceinline__ void mma_f16(float* c, const uint32_t* a, const uint32_t* b) {
    asm volatile(
        "mma.sync.aligned.m16n8k16.row.col.f32.f16.f16.f32 "
        "{%0,%1,%2,%3}, {%4,%5,%6,%7}, {%8,%9}, {%0,%1,%2,%3};"
        : "+f"(c[0]), "+f"(c[1]), "+f"(c[2]), "+f"(c[3])
        : "r"(a[0]), "r"(a[1]), "r"(a[2]), "r"(a[3]), "r"(b[0]), "r"(b[1]));
}

__device__ __forceinline__ void cp16(uint32_t saddr, const void* gaddr) {
    asm volatile("cp.async.cg.shared.global [%0], [%1], 16;" :: "r"(saddr), "l"(gaddr));
}
__device__ __forceinline__ void cp_commit() {
    asm volatile("cp.async.commit_group;" ::: "memory");
}
template <int N>
__device__ __forceinline__ void cp_wait() {
    asm volatile("cp.async.wait_group %0;" :: "n"(N) : "memory");
}

__device__ __forceinline__ void split_f16(float v, __half& hi, __half& lo) {
    hi = __float2half_rn(v);
    lo = __float2half_rn(v - __half2float(hi));
}

// ---------------------------------------------------------------------------
// Weight prep (z-batched): W_z[KTOT, DIM] fp32 -> fp16 hi/lo [DIM, KTOT] slot z
// ---------------------------------------------------------------------------
__global__ void prep_w_kernel(const float* __restrict__ W0,
                              const float* __restrict__ W1,
                              const float* __restrict__ W2,
                              __half* __restrict__ Whi,
                              __half* __restrict__ Wlo)
{
    int z = blockIdx.z;
    const float* W = (z == 0) ? W0 : (z == 1) ? W1 : W2;
    __half* whi = Whi + (size_t)z * WSZ;
    __half* wlo = Wlo + (size_t)z * WSZ;

    __shared__ float ts[32][33];
    int k0 = blockIdx.y * 32, n0 = blockIdx.x * 32;
    int tx = threadIdx.x & 31, ty = threadIdx.x >> 5;   // 32 x 8
    #pragma unroll
    for (int r = 0; r < 4; r++) {
        int k = ty + r * 8;
        ts[k][tx] = W[(size_t)(k0 + k) * DIM + n0 + tx];
    }
    __syncthreads();
    #pragma unroll
    for (int r = 0; r < 4; r++) {
        int n = ty + r * 8;
        float v = ts[tx][n];                      // W[k0+tx][n0+n]
        __half h, l;
        split_f16(v, h, l);
        size_t o = (size_t)(n0 + n) * KTOT + k0 + tx;
        whi[o] = h;
        wlo[o] = l;
    }
}

// ---------------------------------------------------------------------------
// Activation convert: fp32 [TOK,DIM] -> fp16
// ---------------------------------------------------------------------------
__global__ void split_kernel(const float* __restrict__ src,
                             __half* __restrict__ dst)
{
    int i = (blockIdx.x * 256 + threadIdx.x) * 4;
    float4 v = *(const float4*)(src + i);
    __half h[4];
    h[0] = __float2half_rn(v.x);
    h[1] = __float2half_rn(v.y);
    h[2] = __float2half_rn(v.z);
    h[3] = __float2half_rn(v.w);
    *(uint64_t*)(dst + i) = *(uint64_t*)h;
}

// ---------------------------------------------------------------------------
// Tensor-core mixture GEMM via mma.sync (fp16 A + hi/lo B, 2 passes, fp32 acc).
// z-batched: blockIdx.z selects A (via aStride), weight slot, and output.
// 512 threads / 16 warps: 4(M) x 4(N) warp grid, 32x32 warp tile, 3 stages.
// ---------------------------------------------------------------------------
__global__ __launch_bounds__(512)
void circuit_gemm_tc(const __half* __restrict__ A,      // base, + z*aStride
                     size_t aStride,
                     const __half* __restrict__ WhiB,   // slot base
                     const __half* __restrict__ WloB,
                     const float* __restrict__ wgt,     // [TOK, NEXP]
                     float* __restrict__ o0,
                     float* __restrict__ o1,
                     float* __restrict__ o2)
{
    extern __shared__ char smem[];
    __shared__ float swgt[128 * NEXP];
    const uint32_t sb = (uint32_t)__cvta_generic_to_shared(smem);
    int tid = threadIdx.x, lane = tid & 31, wid = tid >> 5;
    int bm = blockIdx.y * 128, bn = blockIdx.x * 128;
    int z  = blockIdx.z;
    const __half* AZ  = A + (size_t)z * aStride;
    const __half* Whi = WhiB + (size_t)z * WSZ;
    const __half* Wlo = WloB + (size_t)z * WSZ;
    float* out = (z == 0) ? o0 : (z == 1) ? o1 : o2;

    // ---- loader role: 4 threads per row, 16-k quarter each ----
    int r  = tid >> 2;                 // 0..127
    int kq = (tid & 3) * 16;           // k quarter
    const __half* ap   = AZ  + (size_t)(bm + r) * DIM + kq;
    const __half* bhip = Whi + (size_t)(bn + r) * KTOT + kq;
    const __half* blop = Wlo + (size_t)(bn + r) * KTOT + kq;
    const uint32_t rowoff = (uint32_t)(r * PAD + kq) * 2;

    auto load_chunk = [&](int c) {
        uint32_t st = sb + (uint32_t)(c % NSTAGE) * STAGE_BYTES;
        int k0 = c * BK;
        int d0 = k0 & (DIM - 1);
        #pragma unroll
        for (int ci = 0; ci < 2; ci++) {
            cp16(st + rowoff + ci * 16,                 ap   + d0 + ci * 8);
            cp16(st + MAT_BYTES + rowoff + ci * 16,     bhip + k0 + ci * 8);
            cp16(st + 2 * MAT_BYTES + rowoff + ci * 16, blop + k0 + ci * 8);
        }
        cp_commit();
    };

    // ---- compute role: 4(M) x 4(N) warp grid, 32x32 warp tile ----
    int wm = (wid >> 2) * 32;
    int wn = (wid & 3) * 32;
    int arow = lane & 15;
    int acol = (lane >> 4) * 8;
    int q    = lane >> 3, rl = lane & 7;
    int brow = wn + ((q >= 2) ? 8 : 0) + rl;
    int bcol = (q & 1) * 8;
    const uint32_t aOff = (uint32_t)((wm + arow) * PAD + acol) * 2;
    const uint32_t bOff = (uint32_t)MAT_BYTES + (uint32_t)(brow * PAD + bcol) * 2;
    int g = lane >> 2;

    float acc[2][4][4];
    float seg[2][4][4];
    #pragma unroll
    for (int i = 0; i < 2; i++)
        #pragma unroll
        for (int j = 0; j < 4; j++)
            #pragma unroll
            for (int e = 0; e < 4; e++) acc[i][j][e] = 0.f;

    // ---- prologue ----
    for (int idx = tid; idx < 128 * NEXP; idx += 512)
        swgt[idx] = wgt[(size_t)(bm + (idx >> 3)) * NEXP + (idx & 7)];
    load_chunk(0);
    load_chunk(1);

    int c = 0;
    for (int e = 0; e < NEXP; e++) {
        #pragma unroll
        for (int i = 0; i < 2; i++)
            #pragma unroll
            for (int j = 0; j < 4; j++)
                #pragma unroll
                for (int t = 0; t < 4; t++) seg[i][j][t] = 0.f;

        for (int dc = 0; dc < 16; dc++, c++) {
            if (c + 1 < NCHUNK) cp_wait<1>(); else cp_wait<0>();
            __syncthreads();
            if (c + 2 < NCHUNK) load_chunk(c + 2);

            uint32_t st = sb + (uint32_t)(c % NSTAGE) * STAGE_BYTES;
            uint32_t aHi = st + aOff;
            uint32_t bHi = st + bOff;

            #pragma unroll
            for (int ks = 0; ks < 4; ks++) {
                uint32_t kb = (uint32_t)(ks * 16) * 2;
                uint32_t bh[4][2], bl[4][2];
                #pragma unroll
                for (int p = 0; p < 2; p++) {
                    uint32_t ba = bHi + (uint32_t)(p * 16 * PAD) * 2 + kb;
                    LDSM4(bh[2*p][0], bh[2*p][1], bh[2*p+1][0], bh[2*p+1][1], ba);
                    LDSM4(bl[2*p][0], bl[2*p][1], bl[2*p+1][0], bl[2*p+1][1], ba + MAT_BYTES);
                }
                uint32_t ah[2][4];
                #pragma unroll
                for (int mt = 0; mt < 2; mt++) {
                    uint32_t aa = aHi + (uint32_t)(mt * 16 * PAD) * 2 + kb;
                    LDSM4(ah[mt][0], ah[mt][1], ah[mt][2], ah[mt][3], aa);
                }
                // pass-major: 8 independent accumulators between same-acc reuse
                #pragma unroll
                for (int mt = 0; mt < 2; mt++)
                    #pragma unroll
                    for (int nt = 0; nt < 4; nt++)
                        mma_f16(seg[mt][nt], ah[mt], bh[nt]);
                #pragma unroll
                for (int mt = 0; mt < 2; mt++)
                    #pragma unroll
                    for (int nt = 0; nt < 4; nt++)
                        mma_f16(seg[mt][nt], ah[mt], bl[nt]);
            }
        }

        // ---- expert boundary: acc += w(row, e) * seg ----
        #pragma unroll
        for (int mt = 0; mt < 2; mt++) {
            float w0 = swgt[(wm + mt * 16 + g) * NEXP + e];
            float w1 = swgt[(wm + mt * 16 + 8 + g) * NEXP + e];
            #pragma unroll
            for (int nt = 0; nt < 4; nt++) {
                acc[mt][nt][0] += w0 * seg[mt][nt][0];
                acc[mt][nt][1] += w0 * seg[mt][nt][1];
                acc[mt][nt][2] += w1 * seg[mt][nt][2];
                acc[mt][nt][3] += w1 * seg[mt][nt][3];
            }
        }
    }

    // ---- epilogue ----
    int tig = lane & 3;
    #pragma unroll
    for (int mt = 0; mt < 2; mt++) {
        #pragma unroll
        for (int nt = 0; nt < 4; nt++) {
            int row = bm + wm + mt * 16 + g;
            int col = bn + wn + nt * 8 + tig * 2;
            *(float2*)(out + (size_t)row * DIM + col) =
                make_float2(acc[mt][nt][0], acc[mt][nt][1]);
            *(float2*)(out + (size_t)(row + 8) * DIM + col) =
                make_float2(acc[mt][nt][2], acc[mt][nt][3]);
        }
    }
}

// ---------------------------------------------------------------------------
// Router: 48 logits per token (8 in / 32 proc / 8 out), softmax8 x2 + top-3
// ---------------------------------------------------------------------------
__global__ void router_kernel(const float* __restrict__ act,
                              const float* __restrict__ Wi,
                              const float* __restrict__ Wp,
                              const float* __restrict__ Wo,
                              float* __restrict__ inw,
                              int*   __restrict__ pidx,
                              float* __restrict__ outw)
{
    int t    = blockIdx.x;
    int tid  = threadIdx.x;
    int lane = tid & 31, warp = tid >> 5;
    __shared__ float xs[DIM];
    __shared__ float lg[48];

    const float* xr = act + (size_t)t * DIM;
    for (int i = tid; i < DIM; i += 128) xs[i] = xr[i];
    __syncthreads();

    for (int l = warp; l < 48; l += 4) {
        const float* wr = (l < 8) ? (Wi + (size_t)l * DIM)
                        : (l < 40) ? (Wp + (size_t)(l - 8) * DIM)
                                   : (Wo + (size_t)(l - 40) * DIM);
        float s = 0.f;
        for (int d = lane; d < DIM; d += 32) s += xs[d] * wr[d];
        #pragma unroll
        for (int off = 16; off > 0; off >>= 1)
            s += __shfl_xor_sync(0xffffffffu, s, off);
        if (lane == 0) lg[l] = s;
    }
    __syncthreads();

    if (tid == 0) {
        float m = lg[0];
        for (int i = 1; i < 8; i++) m = fmaxf(m, lg[i]);
        float e[8], sum = 0.f;
        for (int i = 0; i < 8; i++) { e[i] = expf(lg[i] - m); sum += e[i]; }
        for (int i = 0; i < 8; i++) inw[t * 8 + i] = e[i] / sum;

        bool used[NPROC];
        for (int n = 0; n < NPROC; n++) used[n] = false;
        for (int r = 0; r < TOPK; r++) {
            float best = -INFINITY; int bi = 0;
            for (int n = 0; n < NPROC; n++)
                if (!used[n] && lg[8 + n] > best) { best = lg[8 + n]; bi = n; }
            used[bi] = true;
            pidx[t * TOPK + r] = bi;
        }

        m = lg[40];
        for (int i = 1; i < 8; i++) m = fmaxf(m, lg[40 + i]);
        sum = 0.f;
        for (int i = 0; i < 8; i++) { e[i] = expf(lg[40 + i] - m); sum += e[i]; }
        for (int i = 0; i < 8; i++) outw[t * 8 + i] = e[i] / sum;
    }
}

// ---------------------------------------------------------------------------
// Householder reflections (z-batched): h -= 2 (h.v)/(v.v + 1e-8) v, 3x/token;
// writes fp16 output to slot z.
// ---------------------------------------------------------------------------
__global__ void householder_kernel(const float* __restrict__ hbase,
                                   const float* __restrict__ v0,
                                   const float* __restrict__ v1,
                                   const float* __restrict__ v2,
                                   const int* __restrict__ pidx,
                                   __half* __restrict__ outB)
{
    int t = blockIdx.x, tid = threadIdx.x;
    int z = blockIdx.y;
    int lane = tid & 31, warp = tid >> 5;
    const float* vproc = (z == 0) ? v0 : (z == 1) ? v1 : v2;
    const float* hr = hbase + ((size_t)z * TOK + t) * DIM;
    __half* oh = outB + ((size_t)z * TOK + t) * DIM;

    float hv[4];
    #pragma unroll
    for (int i = 0; i < 4; i++) hv[i] = hr[tid + 256 * i];

    __shared__ float sred[16];

    for (int rfl = 0; rfl < TOPK; rfl++) {
        int idx = pidx[t * TOPK + rfl];
        const float* v = vproc + (size_t)idx * DIM;
        float vr[4];
        float d1 = 0.f, d2 = 0.f;
        #pragma unroll
        for (int i = 0; i < 4; i++) {
            vr[i] = v[tid + 256 * i];
            d1 += hv[i] * vr[i];
            d2 += vr[i] * vr[i];
        }
        #pragma unroll
        for (int off = 16; off > 0; off >>= 1) {
            d1 += __shfl_xor_sync(0xffffffffu, d1, off);
            d2 += __shfl_xor_sync(0xffffffffu, d2, off);
        }
        if (lane == 0) { sred[warp] = d1; sred[8 + warp] = d2; }
        __syncthreads();
        float t1 = 0.f, t2 = 0.f;
        #pragma unroll
        for (int w = 0; w < 8; w++) { t1 += sred[w]; t2 += sred[8 + w]; }
        float f = 2.f * t1 / (t2 + 1e-8f);
        #pragma unroll
        for (int i = 0; i < 4; i++) hv[i] -= f * vr[i];
        __syncthreads();
    }

    #pragma unroll
    for (int i = 0; i < 4; i++)
        oh[tid + 256 * i] = __float2half_rn(hv[i]);
}

// ---------------------------------------------------------------------------
// Causal attention, online softmax (fp32). 32 q-rows per block (512 thr),
// 2 rows per warp sharing K/V smem reads; float4 staging; lane-per-key
// within 32-key batches (math identical to previous rounds).
// Dynamic smem: Ks[32][132] | Vs[32][132] | qs[32][128]
// ---------------------------------------------------------------------------
__global__ __launch_bounds__(512)
void attn_kernel(const float* __restrict__ Q,
                 const float* __restrict__ K,
                 const float* __restrict__ V,
                 float* __restrict__ O)
{
    extern __shared__ float asm_buf[];
    float* Ks = asm_buf + ATTN_KS_OFF;   // [32][KS_STRIDE]
    float* Vs = asm_buf + ATTN_VS_OFF;   // [32][KS_STRIDE]
    float* qs = asm_buf + ATTN_QS_OFF;   // [32][QS_STRIDE]

    const float scale = 0.08838834764831845f;  // 1/sqrt(128)
    int bh = blockIdx.y;
    int b = bh >> 3, hh = bh & 7;
    int q0 = blockIdx.x * 32;
    int tid = threadIdx.x, lane = tid & 31, warp = tid >> 5;

    const float* Qb = Q + (size_t)b * SEQ * DIM + hh * DHEAD;
    const float* Kb = K + (size_t)b * SEQ * DIM + hh * DHEAD;
    const float* Vb = V + (size_t)b * SEQ * DIM + hh * DHEAD;
    float*       Ob = O + (size_t)b * SEQ * DIM + hh * DHEAD;

    int row0 = q0 + warp;        // rows q0 .. q0+15
    int row1 = q0 + 16 + warp;   // rows q0+16 .. q0+31

    // stage q block (float4): 32 rows x 32 float4
    for (int idx = tid; idx < 32 * 32; idx += 512) {
        int j = idx >> 5, d4 = idx & 31;
        ((float4*)&qs[j * QS_STRIDE])[d4] =
            ((const float4*)(Qb + (size_t)(q0 + j) * DIM))[d4];
    }

    float acc0[4] = {0.f, 0.f, 0.f, 0.f};
    float acc1[4] = {0.f, 0.f, 0.f, 0.f};
    float mi0 = -1e30f, li0 = 0.f;
    float mi1 = -1e30f, li1 = 0.f;

    int kend = q0 + 32;   // need keys [0, kend)
    for (int c0 = 0; c0 < kend; c0 += 32) {
        __syncthreads();
        for (int idx = tid; idx < 32 * 32; idx += 512) {
            int j = idx >> 5, d4 = idx & 31;
            ((float4*)&Ks[j * KS_STRIDE])[d4] =
                ((const float4*)(Kb + (size_t)(c0 + j) * DIM))[d4];
            ((float4*)&Vs[j * KS_STRIDE])[d4] =
                ((const float4*)(Vb + (size_t)(c0 + j) * DIM))[d4];
        }
        __syncthreads();

        // lane handles key c0+lane for both rows; shared K reads
        int kg = c0 + lane;
        const float4* kr  = (const float4*)&Ks[lane * KS_STRIDE];
        const float4* qr0 = (const float4*)&qs[warp * QS_STRIDE];
        const float4* qr1 = (const float4*)&qs[(warp + 16) * QS_STRIDE];
        float s0 = 0.f, s1 = 0.f;
        #pragma unroll
        for (int w = 0; w < 32; w++) {
            float4 kk = kr[w];
            float4 qa = qr0[w];
            float4 qb = qr1[w];
            s0 += qa.x * kk.x + qa.y * kk.y + qa.z * kk.z + qa.w * kk.w;
            s1 += qb.x * kk.x + qb.y * kk.y + qb.z * kk.z + qb.w * kk.w;
        }
        s0 *= scale;
        s1 *= scale;
        if (kg > row0) s0 = -1e30f;   // causal mask (exp -> exact 0)
        if (kg > row1) s1 = -1e30f;

        // batch max + single exp per lane, per row
        float mb0 = s0, mb1 = s1;
        #pragma unroll
        for (int off = 16; off > 0; off >>= 1) {
            mb0 = fmaxf(mb0, __shfl_xor_sync(0xffffffffu, mb0, off));
            mb1 = fmaxf(mb1, __shfl_xor_sync(0xffffffffu, mb1, off));
        }
        float mn0 = fmaxf(mi0, mb0);
        float mn1 = fmaxf(mi1, mb1);
        float cr0 = expf(mi0 - mn0);
        float cr1 = expf(mi1 - mn1);
        float p0 = expf(s0 - mn0);
        float p1 = expf(s1 - mn1);
        float ps0 = p0, ps1 = p1;
        #pragma unroll
        for (int off = 16; off > 0; off >>= 1) {
            ps0 += __shfl_xor_sync(0xffffffffu, ps0, off);
            ps1 += __shfl_xor_sync(0xffffffffu, ps1, off);
        }
        li0 = li0 * cr0 + ps0;
        li1 = li1 * cr1 + ps1;

        #pragma unroll
        for (int i = 0; i < 4; i++) { acc0[i] *= cr0; acc1[i] *= cr1; }
        #pragma unroll
        for (int j = 0; j < 32; j++) {
            float pj0 = __shfl_sync(0xffffffffu, p0, j);
            float pj1 = __shfl_sync(0xffffffffu, p1, j);
            float4 vv = *(const float4*)&Vs[j * KS_STRIDE + lane * 4];
            acc0[0] += pj0 * vv.x;  acc0[1] += pj0 * vv.y;
            acc0[2] += pj0 * vv.z;  acc0[3] += pj0 * vv.w;
            acc1[0] += pj1 * vv.x;  acc1[1] += pj1 * vv.y;
            acc1[2] += pj1 * vv.z;  acc1[3] += pj1 * vv.w;
        }
        mi0 = mn0;
        mi1 = mn1;
    }

    float inv0 = 1.f / li0;
    float inv1 = 1.f / li1;
    *(float4*)(Ob + (size_t)row0 * DIM + lane * 4) =
        make_float4(acc0[0] * inv0, acc0[1] * inv0, acc0[2] * inv0, acc0[3] * inv0);
    *(float4*)(Ob + (size_t)row1 * DIM + lane * 4) =
        make_float4(acc1[0] * inv1, acc1[1] * inv1, acc1[2] * inv1, acc1[3] * inv1);
}

// ---------------------------------------------------------------------------
// Launch
// ---------------------------------------------------------------------------
extern "C" void kernel_launch(void* const* d_in, const int* in_sizes, int n_in,
                              void* d_out, int out_size)
{
    const float* x       = (const float*)d_in[0];
    const float* Wr_in   = (const float*)d_in[2];
    const float* Wr_proc = (const float*)d_in[3];
    const float* Wr_out  = (const float*)d_in[4];
    const float* WrO_in  = (const float*)d_in[5];
    const float* WrO_proc= (const float*)d_in[6];
    const float* WrO_out = (const float*)d_in[7];
    const float* Wq_in   = (const float*)d_in[8];
    const float* vq      = (const float*)d_in[9];
    const float* Wq_out  = (const float*)d_in[10];
    const float* Wk_in   = (const float*)d_in[11];
    const float* vk      = (const float*)d_in[12];
    const float* Wk_out  = (const float*)d_in[13];
    const float* Wv_in   = (const float*)d_in[14];
    const float* vv      = (const float*)d_in[15];
    const float* Wv_out  = (const float*)d_in[16];
    const float* Wo_in   = (const float*)d_in[17];
    const float* vo      = (const float*)d_in[18];
    const float* Wo_out  = (const float*)d_in[19];
    float* out = (float*)d_out;

    float *h, *Q, *Kc, *V, *O, *inw, *outw;
    int* pidx;
    __half *whi, *wlo, *xh, *hh;
    cudaGetSymbolAddress((void**)&h,    g_h);
    cudaGetSymbolAddress((void**)&Q,    g_Q);
    cudaGetSymbolAddress((void**)&Kc,   g_Kc);
    cudaGetSymbolAddress((void**)&V,    g_V);
    cudaGetSymbolAddress((void**)&O,    g_O);
    cudaGetSymbolAddress((void**)&inw,  g_inw);
    cudaGetSymbolAddress((void**)&outw, g_outw);
    cudaGetSymbolAddress((void**)&pidx, g_pidx);
    cudaGetSymbolAddress((void**)&whi,  g_whi);
    cudaGetSymbolAddress((void**)&wlo,  g_wlo);
    cudaGetSymbolAddress((void**)&xh,   g_xh);
    cudaGetSymbolAddress((void**)&hh,   g_hh);

    cudaFuncSetAttribute(circuit_gemm_tc,
                         cudaFuncAttributeMaxDynamicSharedMemorySize,
                         SMEM_GEMM_BYTES);
    cudaFuncSetAttribute(attn_kernel,
                         cudaFuncAttributeMaxDynamicSharedMemorySize,
                         SMEM_ATTN_BYTES);

    dim3 gGemm3(DIM / 128, TOK / 128, 3);   // 768 CTAs
    dim3 gGemm1(DIM / 128, TOK / 128, 1);   // 256 CTAs
    dim3 gPrep3(DIM / 32, KTOT / 32, 3);
    dim3 gPrep1(DIM / 32, KTOT / 32, 1);
    int  gSplit = TOK * DIM / (256 * 4);    // 4096

    // ---- Router on x + x convert ----
    router_kernel<<<TOK, 128>>>(x, Wr_in, Wr_proc, Wr_out, inw, pidx, outw);
    split_kernel<<<gSplit, 256>>>(x, xh);

    // ---- Q/K/V in-projections (fused) ----
    prep_w_kernel<<<gPrep3, 256>>>(Wq_in, Wk_in, Wv_in, whi, wlo);
    circuit_gemm_tc<<<gGemm3, 512, SMEM_GEMM_BYTES>>>(
        xh, 0, whi, wlo, inw, h, h + ASZ, h + 2 * ASZ);

    // ---- Householders (fused) ----
    householder_kernel<<<dim3(TOK, 3), 256>>>(h, vq, vk, vv, pidx, hh);

    // ---- Q/K/V out-projections (fused) ----
    prep_w_kernel<<<gPrep3, 256>>>(Wq_out, Wk_out, Wv_out, whi, wlo);
    circuit_gemm_tc<<<gGemm3, 512, SMEM_GEMM_BYTES>>>(
        hh, ASZ, whi, wlo, outw, Q, Kc, V);

    // ---- Attention ----
    attn_kernel<<<dim3(SEQ / 32, NBATCH * NH), 512, SMEM_ATTN_BYTES>>>(Q, Kc, V, O);

    // ---- Router on O + output circuit ----
    router_kernel<<<TOK, 128>>>(O, WrO_in, WrO_proc, WrO_out, inw, pidx, outw);
    split_kernel<<<gSplit, 256>>>(O, xh);
    prep_w_kernel<<<gPrep1, 256>>>(Wo_in, Wo_in, Wo_in, whi, wlo);
    circuit_gemm_tc<<<gGemm1, 512, SMEM_GEMM_BYTES>>>(
        xh, 0, whi, wlo, inw, h, h, h);
    householder_kernel<<<dim3(TOK, 1), 256>>>(h, vo, vo, vo, pidx, hh);
    prep_w_kernel<<<gPrep1, 256>>>(Wo_out, Wo_out, Wo_out, whi, wlo);
    circuit_gemm_tc<<<gGemm1, 512, SMEM_GEMM_BYTES>>>(
        hh, 0, whi, wlo, outw, out, out, out);

    (void)in_sizes; (void)n_in; (void)out_size;
}